// round 9
// baseline (speedup 1.0000x reference)
#include <cuda_runtime.h>
#include <cuda_bf16.h>
#include <math.h>

#define N_NODES 50000
#define N_EDGES 800000
#define D       64
#define N_LAYERS 5
#define N_GRAPHS 256
#define N_CLASSES 10
#define BN_EPS   1e-5f
#define NV (N_NODES * D)

// ---------------- scratch (device globals) ----------------------------------
__device__ float  g_h[NV];
__device__ float  g_k[NV];
__device__ __nv_bfloat16 g_qv[N_NODES * 128];  // per node: q/2 [0..63], v [64..127]
__device__ float  g_s[NV];
__device__ double g_sum[N_LAYERS][D];
__device__ double g_sumsq[N_LAYERS][D];
__device__ float  g_pool[N_GRAPHS * D];
__device__ float  g_cnt[N_GRAPHS];
__device__ float  g_pa[D], g_pb[D];
// CSR
__device__ int g_deg[N_NODES + 1];
__device__ int g_off[N_NODES + 1];
__device__ int g_pos[N_NODES];
__device__ int g_esrc[N_EDGES];

// ---------------- helpers -----------------------------------------------------
__device__ __forceinline__ float tanh_fast(float x) {
    float y;
    asm("tanh.approx.f32 %0, %1;" : "=f"(y) : "f"(x));
    return y;
}
__device__ __forceinline__ float to_tf32(float x) {
    float y;
    asm("cvt.rna.tf32.f32 %0, %1;" : "=f"(y) : "f"(x));
    return y;
}
__device__ __forceinline__ void mma_tf32(float* d,
                                         unsigned a0, unsigned a1, unsigned a2, unsigned a3,
                                         unsigned b0, unsigned b1) {
    asm volatile(
        "mma.sync.aligned.m16n8k8.row.col.f32.tf32.tf32.f32 "
        "{%0,%1,%2,%3}, {%4,%5,%6,%7}, {%8,%9}, {%0,%1,%2,%3};"
        : "+f"(d[0]), "+f"(d[1]), "+f"(d[2]), "+f"(d[3])
        : "r"(a0), "r"(a1), "r"(a2), "r"(a3), "r"(b0), "r"(b1));
}
__device__ __forceinline__ unsigned fbits(float x) { return __float_as_uint(x); }
__device__ __forceinline__ float2 bf2f(unsigned int bits) {
    __nv_bfloat162 b = *reinterpret_cast<__nv_bfloat162*>(&bits);
    return __bfloat1622float2(b);
}

// ---------------- CSR build --------------------------------------------------
__global__ void csr_zero_kernel() {
    int i = blockIdx.x * blockDim.x + threadIdx.x;
    int stride = gridDim.x * blockDim.x;
    for (int j = i; j <= N_NODES; j += stride) g_deg[j] = 0;
    for (int j = i; j < N_GRAPHS * D; j += stride) g_pool[j] = 0.f;
    for (int j = i; j < N_GRAPHS; j += stride) g_cnt[j] = 0.f;
    for (int j = i; j < N_LAYERS * D; j += stride) {
        (&g_sum[0][0])[j] = 0.0;
        (&g_sumsq[0][0])[j] = 0.0;
    }
}

__global__ void csr_hist_kernel(const int* __restrict__ ei) {
    int e = blockIdx.x * blockDim.x + threadIdx.x;
    if (e < N_EDGES) atomicAdd(&g_deg[ei[N_EDGES + e]], 1);
}

__global__ void csr_scan_kernel() {   // single block, 1024 threads
    const int T = 1024;
    const int chunk = (N_NODES + T - 1) / T;
    int t = threadIdx.x;
    int start = t * chunk;
    int end = start + chunk; if (end > N_NODES) end = N_NODES;
    int sum = 0;
    for (int i = start; i < end; i++) sum += g_deg[i];
    __shared__ int sh[T];
    sh[t] = sum;
    __syncthreads();
    for (int ofs = 1; ofs < T; ofs <<= 1) {
        int v = (t >= ofs) ? sh[t - ofs] : 0;
        __syncthreads();
        sh[t] += v;
        __syncthreads();
    }
    int run = sh[t] - sum;   // exclusive prefix
    for (int i = start; i < end; i++) {
        int d = g_deg[i];
        g_off[i] = run;
        g_pos[i] = run;
        run += d;
    }
    if (t == T - 1) g_off[N_NODES] = run;
}

__global__ void csr_scatter_kernel(const int* __restrict__ ei) {
    int e = blockIdx.x * blockDim.x + threadIdx.x;
    if (e >= N_EDGES) return;
    int src = ei[e];
    int dst = ei[N_EDGES + e];
    int p = atomicAdd(&g_pos[dst], 1);
    g_esrc[p] = src;
}

// ---------------- fused GEMM on tensor cores (tf32 mma.sync) -----------------
// grid (ceil(N/64), 2). blockIdx.y=0 -> [Wk|Wq], =1 -> [Wv|Ws]. 256 threads.
// 8 warps: warp w -> m-tile (w&3)*16 rows, n-half (w>>2)*64 cols (8 n-tiles).
#define GEMM_ROWS 64
#define SW_ELEMS (64 * 128)
#define SH_PAD 65
#define SH_ELEMS (64 * SH_PAD)
#define GEMM_SMEM ((SW_ELEMS + SH_ELEMS) * 4)

__global__ void __launch_bounds__(256, 4) gemm4_kernel(
                             const float* __restrict__ X, int use_x, int prev,
                             const float* __restrict__ Wk,
                             const float* __restrict__ Wq,
                             const float* __restrict__ Wv,
                             const float* __restrict__ Ws,
                             const float* __restrict__ bkl,
                             const float* __restrict__ bql,
                             const float* __restrict__ bvl,
                             const float* __restrict__ gamma_prev,
                             const float* __restrict__ beta_prev) {
    extern __shared__ float smem[];
    float* sW = smem;              // [64 k][128 n] tf32
    float* sH = smem + SW_ELEMS;   // [64 r][65]    tf32
    __shared__ float sA[D], sB[D];

    int tid = threadIdx.x;
    int r0 = blockIdx.x * GEMM_ROWS;
    int half = blockIdx.y;        // 0 -> (k,q), 1 -> (v,s)

    if (tid < D) {
        if (use_x) {
            sA[tid] = 1.f; sB[tid] = 0.f;
        } else {
            double mean = g_sum[prev][tid] / (double)N_NODES;
            double var  = g_sumsq[prev][tid] / (double)N_NODES - mean * mean;
            float a = (float)(1.0 / sqrt(var + (double)BN_EPS)) * gamma_prev[tid];
            sA[tid] = a;
            sB[tid] = beta_prev[tid] - (float)mean * a;
        }
    }
    __syncthreads();

    const float* hin = use_x ? X : g_h;
    const float* W0 = half ? Wv : Wk;
    const float* W1 = half ? Ws : Wq;
    // W panel -> smem (tf32-rounded). sW[i*128 + j], j<64 from W0, j>=64 from W1.
    for (int idx = tid; idx < 64 * 32; idx += 256) {
        int i  = idx >> 5;
        int c4 = idx & 31;
        const float* Wsel = (c4 < 16) ? W0 : W1;
        float4 wv = reinterpret_cast<const float4*>(Wsel)[i * 16 + (c4 & 15)];
        wv.x = to_tf32(wv.x); wv.y = to_tf32(wv.y);
        wv.z = to_tf32(wv.z); wv.w = to_tf32(wv.w);
        reinterpret_cast<float4*>(sW)[idx] = wv;
    }
    // H tile -> smem (BN applied, tf32-rounded)
    for (int idx = tid; idx < GEMM_ROWS * 64; idx += 256) {
        int r = idx >> 6, c = idx & 63;
        int gr = r0 + r;
        float hv = (gr < N_NODES) ? hin[gr * 64 + c] : 0.f;
        sH[r * SH_PAD + c] = to_tf32(hv * sA[c] + sB[c]);
    }
    __syncthreads();

    int w = tid >> 5, lane = tid & 31;
    int mw = w & 3;               // m-tile 0..3
    int nh = w >> 2;              // n-half 0..1
    int m0 = mw * 16;
    int g = lane >> 2, t = lane & 3;

    float acc[8][4];
#pragma unroll
    for (int nt = 0; nt < 8; nt++)
#pragma unroll
        for (int c = 0; c < 4; c++) acc[nt][c] = 0.f;

#pragma unroll
    for (int kk = 0; kk < 8; kk++) {
        int k0 = kk * 8;
        unsigned a0 = fbits(sH[(m0 + g) * SH_PAD + k0 + t]);
        unsigned a1 = fbits(sH[(m0 + g + 8) * SH_PAD + k0 + t]);
        unsigned a2 = fbits(sH[(m0 + g) * SH_PAD + k0 + t + 4]);
        unsigned a3 = fbits(sH[(m0 + g + 8) * SH_PAD + k0 + t + 4]);
#pragma unroll
        for (int nt = 0; nt < 8; nt++) {
            int n0 = nh * 64 + nt * 8;
            unsigned b0 = fbits(sW[(k0 + t) * 128 + n0 + g]);
            unsigned b1 = fbits(sW[(k0 + t + 4) * 128 + n0 + g]);
            mma_tf32(acc[nt], a0, a1, a2, a3, b0, b1);
        }
    }

    //  half0,nh0 -> k (fp32,bk)   half0,nh1 -> q (bf16 *0.5, bq)
    //  half1,nh0 -> v (bf16,bv)   half1,nh1 -> s (fp32, 0)
    int is_bf16 = (half == 0) ? nh : (1 - nh);
    const float* bp = (half == 0) ? ((nh == 0) ? bkl : bql)
                                  : ((nh == 0) ? bvl : nullptr);
    float oscale = (half == 0 && nh == 1) ? 0.5f : 1.f;

    int r_lo = r0 + m0 + g;
    int r_hi = r_lo + 8;

#pragma unroll
    for (int nt = 0; nt < 8; nt++) {
        int colm = nt * 8 + 2 * t;        // col within matrix (0..62, even)
        float b0v = bp ? bp[colm] : 0.f;
        float b1v = bp ? bp[colm + 1] : 0.f;
        float lo0 = acc[nt][0] + b0v, lo1 = acc[nt][1] + b1v;
        float hi0 = acc[nt][2] + b0v, hi1 = acc[nt][3] + b1v;
        if (is_bf16) {
            int ofs = (half == 0) ? 0 : 64;
            if (r_lo < N_NODES) {
                __nv_bfloat162 p = __float22bfloat162_rn(
                    make_float2(lo0 * oscale, lo1 * oscale));
                *reinterpret_cast<unsigned*>(&g_qv[(size_t)r_lo * 128 + ofs + colm]) =
                    *reinterpret_cast<unsigned*>(&p);
            }
            if (r_hi < N_NODES) {
                __nv_bfloat162 p = __float22bfloat162_rn(
                    make_float2(hi0 * oscale, hi1 * oscale));
                *reinterpret_cast<unsigned*>(&g_qv[(size_t)r_hi * 128 + ofs + colm]) =
                    *reinterpret_cast<unsigned*>(&p);
            }
        } else {
            float* base = (half == 0) ? g_k : g_s;
            if (r_lo < N_NODES)
                *reinterpret_cast<float2*>(&base[(size_t)r_lo * 64 + colm]) =
                    make_float2(lo0, lo1);
            if (r_hi < N_NODES)
                *reinterpret_cast<float2*>(&base[(size_t)r_hi * 64 + colm]) =
                    make_float2(hi0, hi1);
        }
    }
}

// ---------------- CSR aggregation + epilogue + BN stats ----------------------
// gate = sigmoid(k+q) = 0.5*tanh(0.5k + 0.5q) + 0.5 ; q stored pre-halved.
#define AGG_BLOCKS 1024
#define AGG_WARPS 8

__global__ void __launch_bounds__(256) agg_kernel(int layer,
                                                  const float* __restrict__ bconv_l) {
    int lane = threadIdx.x & 31;
    int w = threadIdx.x >> 5;
    int gw = blockIdx.x * AGG_WARPS + w;
    int nwarps = gridDim.x * AGG_WARPS;

    float2 bc = reinterpret_cast<const float2*>(bconv_l)[lane];

    float lsum0 = 0.f, lsum1 = 0.f, lssq0 = 0.f, lssq1 = 0.f;

    const unsigned int* qv32 = reinterpret_cast<const unsigned int*>(g_qv);

    for (int node = gw; node < N_NODES; node += nwarps) {
        float2 kk = reinterpret_cast<const float2*>(g_k + (size_t)node * 64)[lane];
        float k05x = 0.5f * kk.x, k05y = 0.5f * kk.y;
        float ax = 0.f, ay = 0.f;
        int e0 = g_off[node], e1 = g_off[node + 1];
        for (int base = e0; base < e1; base += 32) {
            int cnt = min(32, e1 - base);
            int sidx = (base + lane < e1) ? __ldg(&g_esrc[base + lane]) : 0;
            int j = 0;
            for (; j + 8 <= cnt; j += 8) {
                int s[8];
                unsigned qb[8], vb[8];
#pragma unroll
                for (int u = 0; u < 8; u++) s[u] = __shfl_sync(0xffffffffu, sidx, j + u);
#pragma unroll
                for (int u = 0; u < 8; u++) {
                    qb[u] = qv32[(size_t)s[u] * 64 + lane];
                    vb[u] = qv32[(size_t)s[u] * 64 + 32 + lane];
                }
#pragma unroll
                for (int u = 0; u < 8; u++) {
                    float2 qq = bf2f(qb[u]), vv = bf2f(vb[u]);
                    ax = fmaf(vv.x, fmaf(tanh_fast(k05x + qq.x), 0.5f, 0.5f), ax);
                    ay = fmaf(vv.y, fmaf(tanh_fast(k05y + qq.y), 0.5f, 0.5f), ay);
                }
            }
            for (; j < cnt; j++) {
                int s = __shfl_sync(0xffffffffu, sidx, j);
                float2 qq = bf2f(qv32[(size_t)s * 64 + lane]);
                float2 vv = bf2f(qv32[(size_t)s * 64 + 32 + lane]);
                ax = fmaf(vv.x, fmaf(tanh_fast(k05x + qq.x), 0.5f, 0.5f), ax);
                ay = fmaf(vv.y, fmaf(tanh_fast(k05y + qq.y), 0.5f, 0.5f), ay);
            }
        }
        float2 sv = reinterpret_cast<const float2*>(g_s + (size_t)node * 64)[lane];
        float t0 = fmaxf(ax + sv.x + bc.x, 0.f);
        float t1 = fmaxf(ay + sv.y + bc.y, 0.f);
        reinterpret_cast<float2*>(g_h + (size_t)node * 64)[lane] = make_float2(t0, t1);
        lsum0 += t0; lsum1 += t1;
        lssq0 += t0 * t0;
        lssq1 += t1 * t1;
    }

    __shared__ float rs[AGG_WARPS][D];
    __shared__ float rq[AGG_WARPS][D];
    rs[w][2 * lane] = lsum0; rs[w][2 * lane + 1] = lsum1;
    rq[w][2 * lane] = lssq0; rq[w][2 * lane + 1] = lssq1;
    __syncthreads();
    if (threadIdx.x < D) {
        double a = 0.0, b = 0.0;
#pragma unroll
        for (int ww = 0; ww < AGG_WARPS; ww++) {
            a += (double)rs[ww][threadIdx.x];
            b += (double)rq[ww][threadIdx.x];
        }
        atomicAdd(&g_sum[layer][threadIdx.x], a);
        atomicAdd(&g_sumsq[layer][threadIdx.x], b);
    }
}

// ---------------- BN params for pooling (layer N_LAYERS-1) -------------------
__global__ void bnparam_kernel(const float* __restrict__ gamma_l,
                               const float* __restrict__ beta_l) {
    int f = threadIdx.x;
    double mean = g_sum[N_LAYERS - 1][f] / (double)N_NODES;
    double var  = g_sumsq[N_LAYERS - 1][f] / (double)N_NODES - mean * mean;
    float a = (float)(1.0 / sqrt(var + (double)BN_EPS)) * gamma_l[f];
    g_pa[f] = a;
    g_pb[f] = beta_l[f] - (float)mean * a;
}

// ---------------- pooling (applies final BN on load) -------------------------
__global__ void pool_kernel(const int* __restrict__ batch) {
    int i = blockIdx.x * blockDim.x + threadIdx.x;
    if (i >= NV) return;
    int n = i >> 6;
    int f = i & 63;
    int b = batch[n];
    float hn = g_h[i] * g_pa[f] + g_pb[f];
    atomicAdd(&g_pool[b * 64 + f], hn);
    if (f == 0) atomicAdd(&g_cnt[b], 1.f);
}

// ---------------- final: pooled @ Wlin + blin, softmax -----------------------
__global__ void final_kernel(const float* __restrict__ Wlin,
                             const float* __restrict__ blin,
                             float* __restrict__ out) {
    __shared__ float sW[D * N_CLASSES];
    __shared__ float sb[N_CLASSES];
    int tid = threadIdx.x;
    for (int i = tid; i < D * N_CLASSES; i += blockDim.x) sW[i] = Wlin[i];
    if (tid < N_CLASSES) sb[tid] = blin[tid];
    __syncthreads();

    int g = tid;
    float cnt = fmaxf(g_cnt[g], 1.f);
    float inv = 1.f / cnt;
    float logits[N_CLASSES];
#pragma unroll
    for (int c = 0; c < N_CLASSES; c++) logits[c] = sb[c];
    for (int f = 0; f < D; f++) {
        float p = g_pool[g * 64 + f] * inv;
#pragma unroll
        for (int c = 0; c < N_CLASSES; c++)
            logits[c] += p * sW[f * N_CLASSES + c];
    }
    float mx = logits[0];
#pragma unroll
    for (int c = 1; c < N_CLASSES; c++) mx = fmaxf(mx, logits[c]);
    float sum = 0.f;
#pragma unroll
    for (int c = 0; c < N_CLASSES; c++) {
        logits[c] = expf(logits[c] - mx);
        sum += logits[c];
    }
    float isum = 1.f / sum;
#pragma unroll
    for (int c = 0; c < N_CLASSES; c++)
        out[g * N_CLASSES + c] = logits[c] * isum;
}

// ---------------- launch -----------------------------------------------------
extern "C" void kernel_launch(void* const* d_in, const int* in_sizes, int n_in,
                              void* d_out, int out_size) {
    const float* X     = (const float*)d_in[0];
    const int*   ei    = (const int*)d_in[1];
    const int*   batch = (const int*)d_in[2];
    const float* Wk    = (const float*)d_in[3];
    const float* Wq    = (const float*)d_in[4];
    const float* Wv    = (const float*)d_in[5];
    const float* Ws    = (const float*)d_in[6];
    const float* bk    = (const float*)d_in[7];
    const float* bq    = (const float*)d_in[8];
    const float* bv    = (const float*)d_in[9];
    const float* bconv = (const float*)d_in[10];
    const float* gamma = (const float*)d_in[11];
    const float* beta  = (const float*)d_in[12];
    const float* Wlin  = (const float*)d_in[13];
    const float* blin  = (const float*)d_in[14];
    float*       out   = (float*)d_out;

    static int smem_set = 0;
    if (!smem_set) {
        cudaFuncSetAttribute(gemm4_kernel,
                             cudaFuncAttributeMaxDynamicSharedMemorySize, GEMM_SMEM);
        smem_set = 1;
    }

    dim3 gemm_grid((N_NODES + GEMM_ROWS - 1) / GEMM_ROWS, 2);
    int edge_blocks = (N_EDGES + 255) / 256;

    csr_zero_kernel<<<128, 256>>>();
    csr_hist_kernel<<<edge_blocks, 256>>>(ei);
    csr_scan_kernel<<<1, 1024>>>();
    gemm4_kernel<<<gemm_grid, 256, GEMM_SMEM>>>(
        X, 1, 0,
        Wk, Wq, Wv, Ws, bk, bq, bv, gamma, beta);
    csr_scatter_kernel<<<edge_blocks, 256>>>(ei);
    agg_kernel<<<AGG_BLOCKS, 256>>>(0, bconv);

    for (int l = 1; l < N_LAYERS; l++) {
        gemm4_kernel<<<gemm_grid, 256, GEMM_SMEM>>>(
            X, 0, l - 1,
            Wk + l * D * D, Wq + l * D * D, Wv + l * D * D, Ws + l * D * D,
            bk + l * D, bq + l * D, bv + l * D,
            gamma + (l - 1) * D, beta + (l - 1) * D);
        agg_kernel<<<AGG_BLOCKS, 256>>>(l, bconv + l * D);
    }

    bnparam_kernel<<<1, 64>>>(gamma + (N_LAYERS - 1) * D, beta + (N_LAYERS - 1) * D);
    pool_kernel<<<(NV + 255) / 256, 256>>>(batch);
    final_kernel<<<1, 256>>>(Wlin, blin, out);
}

// round 10
// speedup vs baseline: 1.1735x; 1.1735x over previous
#include <cuda_runtime.h>
#include <cuda_bf16.h>
#include <math.h>

#define N_NODES 50000
#define N_EDGES 800000
#define D       64
#define N_LAYERS 5
#define N_GRAPHS 256
#define N_CLASSES 10
#define BN_EPS   1e-5f
#define NV (N_NODES * D)

// ---------------- scratch (device globals) ----------------------------------
__device__ float  g_h[NV];
__device__ float  g_k[NV];
__device__ __nv_bfloat16 g_qv[N_NODES * 128];  // per node: q/2 [0..63], v [64..127]
__device__ float  g_s[NV];
__device__ double g_sum[N_LAYERS][D];
__device__ double g_sumsq[N_LAYERS][D];
__device__ float  g_pool[N_GRAPHS * D];
__device__ float  g_cnt[N_GRAPHS];
__device__ float  g_pa[D], g_pb[D];
// CSR
__device__ int g_deg[N_NODES + 1];
__device__ int g_off[N_NODES + 1];
__device__ int g_pos[N_NODES];
__device__ int g_esrc[N_EDGES];

// ---------------- helpers -----------------------------------------------------
__device__ __forceinline__ float tanh_fast(float x) {
    float y;
    asm("tanh.approx.f32 %0, %1;" : "=f"(y) : "f"(x));
    return y;
}
__device__ __forceinline__ float to_tf32(float x) {
    float y;
    asm("cvt.rna.tf32.f32 %0, %1;" : "=f"(y) : "f"(x));
    return y;
}
__device__ __forceinline__ void mma_tf32(float* d,
                                         unsigned a0, unsigned a1, unsigned a2, unsigned a3,
                                         unsigned b0, unsigned b1) {
    asm volatile(
        "mma.sync.aligned.m16n8k8.row.col.f32.tf32.tf32.f32 "
        "{%0,%1,%2,%3}, {%4,%5,%6,%7}, {%8,%9}, {%0,%1,%2,%3};"
        : "+f"(d[0]), "+f"(d[1]), "+f"(d[2]), "+f"(d[3])
        : "r"(a0), "r"(a1), "r"(a2), "r"(a3), "r"(b0), "r"(b1));
}
__device__ __forceinline__ unsigned fbits(float x) { return __float_as_uint(x); }
__device__ __forceinline__ float2 bf2f(unsigned int bits) {
    __nv_bfloat162 b = *reinterpret_cast<__nv_bfloat162*>(&bits);
    return __bfloat1622float2(b);
}

// ---------------- CSR build --------------------------------------------------
__global__ void csr_zero_kernel() {
    int i = blockIdx.x * blockDim.x + threadIdx.x;
    int stride = gridDim.x * blockDim.x;
    for (int j = i; j <= N_NODES; j += stride) g_deg[j] = 0;
    for (int j = i; j < N_GRAPHS * D; j += stride) g_pool[j] = 0.f;
    for (int j = i; j < N_GRAPHS; j += stride) g_cnt[j] = 0.f;
    for (int j = i; j < N_LAYERS * D; j += stride) {
        (&g_sum[0][0])[j] = 0.0;
        (&g_sumsq[0][0])[j] = 0.0;
    }
}

__global__ void csr_hist_kernel(const int* __restrict__ ei) {
    int e = blockIdx.x * blockDim.x + threadIdx.x;
    if (e < N_EDGES) atomicAdd(&g_deg[ei[N_EDGES + e]], 1);
}

__global__ void csr_scan_kernel() {   // single block, 1024 threads
    const int T = 1024;
    const int chunk = (N_NODES + T - 1) / T;
    int t = threadIdx.x;
    int start = t * chunk;
    int end = start + chunk; if (end > N_NODES) end = N_NODES;
    int sum = 0;
    for (int i = start; i < end; i++) sum += g_deg[i];
    __shared__ int sh[T];
    sh[t] = sum;
    __syncthreads();
    for (int ofs = 1; ofs < T; ofs <<= 1) {
        int v = (t >= ofs) ? sh[t - ofs] : 0;
        __syncthreads();
        sh[t] += v;
        __syncthreads();
    }
    int run = sh[t] - sum;   // exclusive prefix
    for (int i = start; i < end; i++) {
        int d = g_deg[i];
        g_off[i] = run;
        g_pos[i] = run;
        run += d;
    }
    if (t == T - 1) g_off[N_NODES] = run;
}

__global__ void csr_scatter_kernel(const int* __restrict__ ei) {
    int e = blockIdx.x * blockDim.x + threadIdx.x;
    if (e >= N_EDGES) return;
    int src = ei[e];
    int dst = ei[N_EDGES + e];
    int p = atomicAdd(&g_pos[dst], 1);
    g_esrc[p] = src;
}

// ---------------- fused GEMM on tensor cores (tf32 mma.sync) -----------------
// grid (ceil(N/64), 2). blockIdx.y=0 -> [Wk|Wq], =1 -> [Wv|Ws]. 256 threads.
// Bank-conflict-free pads: sW stride 136 (≡8 mod 32: t*8+g distinct),
//                          sH stride 68  (≡4 mod 32: g*4+t distinct).
#define GEMM_ROWS 64
#define SW_STRIDE 136
#define SW_ELEMS (64 * SW_STRIDE)
#define SH_PAD 68
#define SH_ELEMS (64 * SH_PAD)
#define GEMM_SMEM ((SW_ELEMS + SH_ELEMS) * 4)

__global__ void __launch_bounds__(256, 4) gemm4_kernel(
                             const float* __restrict__ X, int use_x, int prev,
                             const float* __restrict__ Wk,
                             const float* __restrict__ Wq,
                             const float* __restrict__ Wv,
                             const float* __restrict__ Ws,
                             const float* __restrict__ bkl,
                             const float* __restrict__ bql,
                             const float* __restrict__ bvl,
                             const float* __restrict__ gamma_prev,
                             const float* __restrict__ beta_prev) {
    extern __shared__ float smem[];
    float* sW = smem;              // [64 k][136] tf32 (cols 0..127 used)
    float* sH = smem + SW_ELEMS;   // [64 r][68]  tf32
    __shared__ float sA[D], sB[D];

    int tid = threadIdx.x;
    int r0 = blockIdx.x * GEMM_ROWS;
    int half = blockIdx.y;        // 0 -> (k,q), 1 -> (v,s)

    if (tid < D) {
        if (use_x) {
            sA[tid] = 1.f; sB[tid] = 0.f;
        } else {
            double mean = g_sum[prev][tid] / (double)N_NODES;
            double var  = g_sumsq[prev][tid] / (double)N_NODES - mean * mean;
            float a = (float)(1.0 / sqrt(var + (double)BN_EPS)) * gamma_prev[tid];
            sA[tid] = a;
            sB[tid] = beta_prev[tid] - (float)mean * a;
        }
    }
    __syncthreads();

    const float* hin = use_x ? X : g_h;
    const float* W0 = half ? Wv : Wk;
    const float* W1 = half ? Ws : Wq;
    // W panel -> smem (tf32-rounded). Row i: cols [0..63] from W0, [64..127] from W1.
    for (int idx = tid; idx < 64 * 32; idx += 256) {
        int i  = idx >> 5;
        int c4 = idx & 31;
        const float* Wsel = (c4 < 16) ? W0 : W1;
        float4 wv = reinterpret_cast<const float4*>(Wsel)[i * 16 + (c4 & 15)];
        wv.x = to_tf32(wv.x); wv.y = to_tf32(wv.y);
        wv.z = to_tf32(wv.z); wv.w = to_tf32(wv.w);
        reinterpret_cast<float4*>(&sW[i * SW_STRIDE])[c4] = wv;
    }
    // H tile -> smem (BN applied, tf32-rounded)
    for (int idx = tid; idx < GEMM_ROWS * 64; idx += 256) {
        int r = idx >> 6, c = idx & 63;
        int gr = r0 + r;
        float hv = (gr < N_NODES) ? hin[gr * 64 + c] : 0.f;
        sH[r * SH_PAD + c] = to_tf32(hv * sA[c] + sB[c]);
    }
    __syncthreads();

    int w = tid >> 5, lane = tid & 31;
    int mw = w & 3;               // m-tile 0..3
    int nh = w >> 2;              // n-half 0..1
    int m0 = mw * 16;
    int g = lane >> 2, t = lane & 3;

    float acc[8][4];
#pragma unroll
    for (int nt = 0; nt < 8; nt++)
#pragma unroll
        for (int c = 0; c < 4; c++) acc[nt][c] = 0.f;

#pragma unroll
    for (int kk = 0; kk < 8; kk++) {
        int k0 = kk * 8;
        unsigned a0 = fbits(sH[(m0 + g) * SH_PAD + k0 + t]);
        unsigned a1 = fbits(sH[(m0 + g + 8) * SH_PAD + k0 + t]);
        unsigned a2 = fbits(sH[(m0 + g) * SH_PAD + k0 + t + 4]);
        unsigned a3 = fbits(sH[(m0 + g + 8) * SH_PAD + k0 + t + 4]);
#pragma unroll
        for (int nt = 0; nt < 8; nt++) {
            int n0 = nh * 64 + nt * 8;
            unsigned b0 = fbits(sW[(k0 + t) * SW_STRIDE + n0 + g]);
            unsigned b1 = fbits(sW[(k0 + t + 4) * SW_STRIDE + n0 + g]);
            mma_tf32(acc[nt], a0, a1, a2, a3, b0, b1);
        }
    }

    //  half0,nh0 -> k (fp32,bk)   half0,nh1 -> q (bf16 *0.5, bq)
    //  half1,nh0 -> v (bf16,bv)   half1,nh1 -> s (fp32, 0)
    int is_bf16 = (half == 0) ? nh : (1 - nh);
    const float* bp = (half == 0) ? ((nh == 0) ? bkl : bql)
                                  : ((nh == 0) ? bvl : nullptr);
    float oscale = (half == 0 && nh == 1) ? 0.5f : 1.f;

    int r_lo = r0 + m0 + g;
    int r_hi = r_lo + 8;

#pragma unroll
    for (int nt = 0; nt < 8; nt++) {
        int colm = nt * 8 + 2 * t;        // col within matrix (0..62, even)
        float b0v = bp ? bp[colm] : 0.f;
        float b1v = bp ? bp[colm + 1] : 0.f;
        float lo0 = acc[nt][0] + b0v, lo1 = acc[nt][1] + b1v;
        float hi0 = acc[nt][2] + b0v, hi1 = acc[nt][3] + b1v;
        if (is_bf16) {
            int ofs = (half == 0) ? 0 : 64;
            if (r_lo < N_NODES) {
                __nv_bfloat162 p = __float22bfloat162_rn(
                    make_float2(lo0 * oscale, lo1 * oscale));
                *reinterpret_cast<unsigned*>(&g_qv[(size_t)r_lo * 128 + ofs + colm]) =
                    *reinterpret_cast<unsigned*>(&p);
            }
            if (r_hi < N_NODES) {
                __nv_bfloat162 p = __float22bfloat162_rn(
                    make_float2(hi0 * oscale, hi1 * oscale));
                *reinterpret_cast<unsigned*>(&g_qv[(size_t)r_hi * 128 + ofs + colm]) =
                    *reinterpret_cast<unsigned*>(&p);
            }
        } else {
            float* base = (half == 0) ? g_k : g_s;
            if (r_lo < N_NODES)
                *reinterpret_cast<float2*>(&base[(size_t)r_lo * 64 + colm]) =
                    make_float2(lo0, lo1);
            if (r_hi < N_NODES)
                *reinterpret_cast<float2*>(&base[(size_t)r_hi * 64 + colm]) =
                    make_float2(hi0, hi1);
        }
    }
}

// ---------------- CSR aggregation + epilogue + BN stats ----------------------
// gate = sigmoid(k+q) = 0.5*tanh(0.5k + 0.5q) + 0.5 ; q stored pre-halved.
#define AGG_BLOCKS 1024
#define AGG_WARPS 8

__global__ void __launch_bounds__(256) agg_kernel(int layer,
                                                  const float* __restrict__ bconv_l) {
    int lane = threadIdx.x & 31;
    int w = threadIdx.x >> 5;
    int gw = blockIdx.x * AGG_WARPS + w;
    int nwarps = gridDim.x * AGG_WARPS;

    float2 bc = reinterpret_cast<const float2*>(bconv_l)[lane];

    float lsum0 = 0.f, lsum1 = 0.f, lssq0 = 0.f, lssq1 = 0.f;

    const unsigned int* qv32 = reinterpret_cast<const unsigned int*>(g_qv);

    for (int node = gw; node < N_NODES; node += nwarps) {
        float2 kk = reinterpret_cast<const float2*>(g_k + (size_t)node * 64)[lane];
        float k05x = 0.5f * kk.x, k05y = 0.5f * kk.y;
        float ax = 0.f, ay = 0.f;
        int e0 = g_off[node], e1 = g_off[node + 1];
        for (int base = e0; base < e1; base += 32) {
            int cnt = min(32, e1 - base);
            int sidx = (base + lane < e1) ? __ldg(&g_esrc[base + lane]) : 0;
            int j = 0;
            for (; j + 8 <= cnt; j += 8) {
                int s[8];
                unsigned qb[8], vb[8];
#pragma unroll
                for (int u = 0; u < 8; u++) s[u] = __shfl_sync(0xffffffffu, sidx, j + u);
#pragma unroll
                for (int u = 0; u < 8; u++) {
                    qb[u] = qv32[(size_t)s[u] * 64 + lane];
                    vb[u] = qv32[(size_t)s[u] * 64 + 32 + lane];
                }
#pragma unroll
                for (int u = 0; u < 8; u++) {
                    float2 qq = bf2f(qb[u]), vv = bf2f(vb[u]);
                    ax = fmaf(vv.x, fmaf(tanh_fast(k05x + qq.x), 0.5f, 0.5f), ax);
                    ay = fmaf(vv.y, fmaf(tanh_fast(k05y + qq.y), 0.5f, 0.5f), ay);
                }
            }
            for (; j < cnt; j++) {
                int s = __shfl_sync(0xffffffffu, sidx, j);
                float2 qq = bf2f(qv32[(size_t)s * 64 + lane]);
                float2 vv = bf2f(qv32[(size_t)s * 64 + 32 + lane]);
                ax = fmaf(vv.x, fmaf(tanh_fast(k05x + qq.x), 0.5f, 0.5f), ax);
                ay = fmaf(vv.y, fmaf(tanh_fast(k05y + qq.y), 0.5f, 0.5f), ay);
            }
        }
        float2 sv = reinterpret_cast<const float2*>(g_s + (size_t)node * 64)[lane];
        float t0 = fmaxf(ax + sv.x + bc.x, 0.f);
        float t1 = fmaxf(ay + sv.y + bc.y, 0.f);
        reinterpret_cast<float2*>(g_h + (size_t)node * 64)[lane] = make_float2(t0, t1);
        lsum0 += t0; lsum1 += t1;
        lssq0 += t0 * t0;
        lssq1 += t1 * t1;
    }

    __shared__ float rs[AGG_WARPS][D];
    __shared__ float rq[AGG_WARPS][D];
    rs[w][2 * lane] = lsum0; rs[w][2 * lane + 1] = lsum1;
    rq[w][2 * lane] = lssq0; rq[w][2 * lane + 1] = lssq1;
    __syncthreads();
    if (threadIdx.x < D) {
        double a = 0.0, b = 0.0;
#pragma unroll
        for (int ww = 0; ww < AGG_WARPS; ww++) {
            a += (double)rs[ww][threadIdx.x];
            b += (double)rq[ww][threadIdx.x];
        }
        atomicAdd(&g_sum[layer][threadIdx.x], a);
        atomicAdd(&g_sumsq[layer][threadIdx.x], b);
    }
}

// ---------------- BN params for pooling (layer N_LAYERS-1) -------------------
__global__ void bnparam_kernel(const float* __restrict__ gamma_l,
                               const float* __restrict__ beta_l) {
    int f = threadIdx.x;
    double mean = g_sum[N_LAYERS - 1][f] / (double)N_NODES;
    double var  = g_sumsq[N_LAYERS - 1][f] / (double)N_NODES - mean * mean;
    float a = (float)(1.0 / sqrt(var + (double)BN_EPS)) * gamma_l[f];
    g_pa[f] = a;
    g_pb[f] = beta_l[f] - (float)mean * a;
}

// ---------------- pooling (applies final BN on load) -------------------------
__global__ void pool_kernel(const int* __restrict__ batch) {
    int i = blockIdx.x * blockDim.x + threadIdx.x;
    if (i >= NV) return;
    int n = i >> 6;
    int f = i & 63;
    int b = batch[n];
    float hn = g_h[i] * g_pa[f] + g_pb[f];
    atomicAdd(&g_pool[b * 64 + f], hn);
    if (f == 0) atomicAdd(&g_cnt[b], 1.f);
}

// ---------------- final: pooled @ Wlin + blin, softmax -----------------------
__global__ void final_kernel(const float* __restrict__ Wlin,
                             const float* __restrict__ blin,
                             float* __restrict__ out) {
    __shared__ float sW[D * N_CLASSES];
    __shared__ float sb[N_CLASSES];
    int tid = threadIdx.x;
    for (int i = tid; i < D * N_CLASSES; i += blockDim.x) sW[i] = Wlin[i];
    if (tid < N_CLASSES) sb[tid] = blin[tid];
    __syncthreads();

    int g = tid;
    float cnt = fmaxf(g_cnt[g], 1.f);
    float inv = 1.f / cnt;
    float logits[N_CLASSES];
#pragma unroll
    for (int c = 0; c < N_CLASSES; c++) logits[c] = sb[c];
    for (int f = 0; f < D; f++) {
        float p = g_pool[g * 64 + f] * inv;
#pragma unroll
        for (int c = 0; c < N_CLASSES; c++)
            logits[c] += p * sW[f * N_CLASSES + c];
    }
    float mx = logits[0];
#pragma unroll
    for (int c = 1; c < N_CLASSES; c++) mx = fmaxf(mx, logits[c]);
    float sum = 0.f;
#pragma unroll
    for (int c = 0; c < N_CLASSES; c++) {
        logits[c] = expf(logits[c] - mx);
        sum += logits[c];
    }
    float isum = 1.f / sum;
#pragma unroll
    for (int c = 0; c < N_CLASSES; c++)
        out[g * N_CLASSES + c] = logits[c] * isum;
}

// ---------------- launch -----------------------------------------------------
extern "C" void kernel_launch(void* const* d_in, const int* in_sizes, int n_in,
                              void* d_out, int out_size) {
    const float* X     = (const float*)d_in[0];
    const int*   ei    = (const int*)d_in[1];
    const int*   batch = (const int*)d_in[2];
    const float* Wk    = (const float*)d_in[3];
    const float* Wq    = (const float*)d_in[4];
    const float* Wv    = (const float*)d_in[5];
    const float* Ws    = (const float*)d_in[6];
    const float* bk    = (const float*)d_in[7];
    const float* bq    = (const float*)d_in[8];
    const float* bv    = (const float*)d_in[9];
    const float* bconv = (const float*)d_in[10];
    const float* gamma = (const float*)d_in[11];
    const float* beta  = (const float*)d_in[12];
    const float* Wlin  = (const float*)d_in[13];
    const float* blin  = (const float*)d_in[14];
    float*       out   = (float*)d_out;

    static int smem_set = 0;
    if (!smem_set) {
        cudaFuncSetAttribute(gemm4_kernel,
                             cudaFuncAttributeMaxDynamicSharedMemorySize, GEMM_SMEM);
        smem_set = 1;
    }

    dim3 gemm_grid((N_NODES + GEMM_ROWS - 1) / GEMM_ROWS, 2);
    int edge_blocks = (N_EDGES + 255) / 256;

    csr_zero_kernel<<<128, 256>>>();
    csr_hist_kernel<<<edge_blocks, 256>>>(ei);
    csr_scan_kernel<<<1, 1024>>>();
    gemm4_kernel<<<gemm_grid, 256, GEMM_SMEM>>>(
        X, 1, 0,
        Wk, Wq, Wv, Ws, bk, bq, bv, gamma, beta);
    csr_scatter_kernel<<<edge_blocks, 256>>>(ei);
    agg_kernel<<<AGG_BLOCKS, 256>>>(0, bconv);

    for (int l = 1; l < N_LAYERS; l++) {
        gemm4_kernel<<<gemm_grid, 256, GEMM_SMEM>>>(
            X, 0, l - 1,
            Wk + l * D * D, Wq + l * D * D, Wv + l * D * D, Ws + l * D * D,
            bk + l * D, bq + l * D, bv + l * D,
            gamma + (l - 1) * D, beta + (l - 1) * D);
        agg_kernel<<<AGG_BLOCKS, 256>>>(l, bconv + l * D);
    }

    bnparam_kernel<<<1, 64>>>(gamma + (N_LAYERS - 1) * D, beta + (N_LAYERS - 1) * D);
    pool_kernel<<<(NV + 255) / 256, 256>>>(batch);
    final_kernel<<<1, 256>>>(Wlin, blin, out);
}

// round 11
// speedup vs baseline: 1.3404x; 1.1422x over previous
#include <cuda_runtime.h>
#include <cuda_bf16.h>
#include <math.h>

#define N_NODES 50000
#define N_EDGES 800000
#define D       64
#define N_LAYERS 5
#define N_GRAPHS 256
#define N_CLASSES 10
#define BN_EPS   1e-5f
#define NV (N_NODES * D)

// ---------------- scratch (device globals) ----------------------------------
__device__ float  g_h[NV];
__device__ float  g_k[NV];
__device__ __nv_bfloat16 g_qv[N_NODES * 128];  // per node: q/2 [0..63], v [64..127]
__device__ float  g_s[NV];
__device__ double g_sum[N_LAYERS][D];
__device__ double g_sumsq[N_LAYERS][D];
__device__ float  g_pool[N_GRAPHS * D];
__device__ float  g_cnt[N_GRAPHS];
__device__ float  g_pa[D], g_pb[D];
// CSR
__device__ int g_deg[N_NODES + 1];
__device__ int g_off[N_NODES + 1];
__device__ int g_pos[N_NODES];
__device__ int g_esrc[N_EDGES];

// ---------------- helpers -----------------------------------------------------
__device__ __forceinline__ float tanh_fast(float x) {
    float y;
    asm("tanh.approx.f32 %0, %1;" : "=f"(y) : "f"(x));
    return y;
}
__device__ __forceinline__ float to_tf32(float x) {
    float y;
    asm("cvt.rna.tf32.f32 %0, %1;" : "=f"(y) : "f"(x));
    return y;
}
__device__ __forceinline__ void mma_tf32(float* d,
                                         unsigned a0, unsigned a1, unsigned a2, unsigned a3,
                                         unsigned b0, unsigned b1) {
    asm volatile(
        "mma.sync.aligned.m16n8k8.row.col.f32.tf32.tf32.f32 "
        "{%0,%1,%2,%3}, {%4,%5,%6,%7}, {%8,%9}, {%0,%1,%2,%3};"
        : "+f"(d[0]), "+f"(d[1]), "+f"(d[2]), "+f"(d[3])
        : "r"(a0), "r"(a1), "r"(a2), "r"(a3), "r"(b0), "r"(b1));
}
__device__ __forceinline__ unsigned fbits(float x) { return __float_as_uint(x); }
__device__ __forceinline__ float2 bf2f(unsigned int bits) {
    __nv_bfloat162 b = *reinterpret_cast<__nv_bfloat162*>(&bits);
    return __bfloat1622float2(b);
}

// ---------------- CSR build --------------------------------------------------
__global__ void csr_zero_kernel() {
    int i = blockIdx.x * blockDim.x + threadIdx.x;
    int stride = gridDim.x * blockDim.x;
    for (int j = i; j <= N_NODES; j += stride) g_deg[j] = 0;
    for (int j = i; j < N_GRAPHS * D; j += stride) g_pool[j] = 0.f;
    for (int j = i; j < N_GRAPHS; j += stride) g_cnt[j] = 0.f;
    for (int j = i; j < N_LAYERS * D; j += stride) {
        (&g_sum[0][0])[j] = 0.0;
        (&g_sumsq[0][0])[j] = 0.0;
    }
}

__global__ void csr_hist_kernel(const int* __restrict__ ei) {
    int e = blockIdx.x * blockDim.x + threadIdx.x;
    if (e < N_EDGES) atomicAdd(&g_deg[ei[N_EDGES + e]], 1);
}

__global__ void csr_scan_kernel() {   // single block, 1024 threads
    const int T = 1024;
    const int chunk = (N_NODES + T - 1) / T;
    int t = threadIdx.x;
    int start = t * chunk;
    int end = start + chunk; if (end > N_NODES) end = N_NODES;
    int sum = 0;
    for (int i = start; i < end; i++) sum += g_deg[i];
    __shared__ int sh[T];
    sh[t] = sum;
    __syncthreads();
    for (int ofs = 1; ofs < T; ofs <<= 1) {
        int v = (t >= ofs) ? sh[t - ofs] : 0;
        __syncthreads();
        sh[t] += v;
        __syncthreads();
    }
    int run = sh[t] - sum;   // exclusive prefix
    for (int i = start; i < end; i++) {
        int d = g_deg[i];
        g_off[i] = run;
        g_pos[i] = run;
        run += d;
    }
    if (t == T - 1) g_off[N_NODES] = run;
}

__global__ void csr_scatter_kernel(const int* __restrict__ ei) {
    int e = blockIdx.x * blockDim.x + threadIdx.x;
    if (e >= N_EDGES) return;
    int src = ei[e];
    int dst = ei[N_EDGES + e];
    int p = atomicAdd(&g_pos[dst], 1);
    g_esrc[p] = src;
}

// ---------------- fused GEMM on tensor cores (tf32 mma.sync) -----------------
// grid (ceil(N/64), 2). blockIdx.y=0 -> [Wk|Wq], =1 -> [Wv|Ws]. 256 threads.
// Bank-conflict-free pads: sW stride 136 (≡8 mod 32), sH stride 68 (≡4 mod 32).
#define GEMM_ROWS 64
#define SW_STRIDE 136
#define SW_ELEMS (64 * SW_STRIDE)
#define SH_PAD 68
#define SH_ELEMS (64 * SH_PAD)
#define GEMM_SMEM ((SW_ELEMS + SH_ELEMS) * 4)

__global__ void __launch_bounds__(256, 4) gemm4_kernel(
                             const float* __restrict__ X, int use_x, int prev,
                             const float* __restrict__ Wk,
                             const float* __restrict__ Wq,
                             const float* __restrict__ Wv,
                             const float* __restrict__ Ws,
                             const float* __restrict__ bkl,
                             const float* __restrict__ bql,
                             const float* __restrict__ bvl,
                             const float* __restrict__ gamma_prev,
                             const float* __restrict__ beta_prev) {
    extern __shared__ float smem[];
    float* sW = smem;              // [64 k][136] tf32 (cols 0..127 used)
    float* sH = smem + SW_ELEMS;   // [64 r][68]  tf32
    __shared__ float sA[D], sB[D];

    int tid = threadIdx.x;
    int r0 = blockIdx.x * GEMM_ROWS;
    int half = blockIdx.y;        // 0 -> (k,q), 1 -> (v,s)

    if (tid < D) {
        if (use_x) {
            sA[tid] = 1.f; sB[tid] = 0.f;
        } else {
            double mean = g_sum[prev][tid] / (double)N_NODES;
            double var  = g_sumsq[prev][tid] / (double)N_NODES - mean * mean;
            float a = (float)(1.0 / sqrt(var + (double)BN_EPS)) * gamma_prev[tid];
            sA[tid] = a;
            sB[tid] = beta_prev[tid] - (float)mean * a;
        }
    }
    __syncthreads();

    const float* hin = use_x ? X : g_h;
    const float* W0 = half ? Wv : Wk;
    const float* W1 = half ? Ws : Wq;
    // W panel -> smem (tf32-rounded). Row i: cols [0..63] from W0, [64..127] from W1.
    for (int idx = tid; idx < 64 * 32; idx += 256) {
        int i  = idx >> 5;
        int c4 = idx & 31;
        const float* Wsel = (c4 < 16) ? W0 : W1;
        float4 wv = reinterpret_cast<const float4*>(Wsel)[i * 16 + (c4 & 15)];
        wv.x = to_tf32(wv.x); wv.y = to_tf32(wv.y);
        wv.z = to_tf32(wv.z); wv.w = to_tf32(wv.w);
        reinterpret_cast<float4*>(&sW[i * SW_STRIDE])[c4] = wv;
    }
    // H tile -> smem (BN applied, tf32-rounded)
    for (int idx = tid; idx < GEMM_ROWS * 64; idx += 256) {
        int r = idx >> 6, c = idx & 63;
        int gr = r0 + r;
        float hv = (gr < N_NODES) ? hin[gr * 64 + c] : 0.f;
        sH[r * SH_PAD + c] = to_tf32(hv * sA[c] + sB[c]);
    }
    __syncthreads();

    int w = tid >> 5, lane = tid & 31;
    int mw = w & 3;               // m-tile 0..3
    int nh = w >> 2;              // n-half 0..1
    int m0 = mw * 16;
    int g = lane >> 2, t = lane & 3;

    float acc[8][4];
#pragma unroll
    for (int nt = 0; nt < 8; nt++)
#pragma unroll
        for (int c = 0; c < 4; c++) acc[nt][c] = 0.f;

#pragma unroll
    for (int kk = 0; kk < 8; kk++) {
        int k0 = kk * 8;
        unsigned a0 = fbits(sH[(m0 + g) * SH_PAD + k0 + t]);
        unsigned a1 = fbits(sH[(m0 + g + 8) * SH_PAD + k0 + t]);
        unsigned a2 = fbits(sH[(m0 + g) * SH_PAD + k0 + t + 4]);
        unsigned a3 = fbits(sH[(m0 + g + 8) * SH_PAD + k0 + t + 4]);
#pragma unroll
        for (int nt = 0; nt < 8; nt++) {
            int n0 = nh * 64 + nt * 8;
            unsigned b0 = fbits(sW[(k0 + t) * SW_STRIDE + n0 + g]);
            unsigned b1 = fbits(sW[(k0 + t + 4) * SW_STRIDE + n0 + g]);
            mma_tf32(acc[nt], a0, a1, a2, a3, b0, b1);
        }
    }

    //  half0,nh0 -> k (fp32,bk)   half0,nh1 -> q (bf16 *0.5, bq)
    //  half1,nh0 -> v (bf16,bv)   half1,nh1 -> s (fp32, 0)
    int is_bf16 = (half == 0) ? nh : (1 - nh);
    const float* bp = (half == 0) ? ((nh == 0) ? bkl : bql)
                                  : ((nh == 0) ? bvl : nullptr);
    float oscale = (half == 0 && nh == 1) ? 0.5f : 1.f;

    int r_lo = r0 + m0 + g;
    int r_hi = r_lo + 8;

#pragma unroll
    for (int nt = 0; nt < 8; nt++) {
        int colm = nt * 8 + 2 * t;        // col within matrix (0..62, even)
        float b0v = bp ? bp[colm] : 0.f;
        float b1v = bp ? bp[colm + 1] : 0.f;
        float lo0 = acc[nt][0] + b0v, lo1 = acc[nt][1] + b1v;
        float hi0 = acc[nt][2] + b0v, hi1 = acc[nt][3] + b1v;
        if (is_bf16) {
            int ofs = (half == 0) ? 0 : 64;
            if (r_lo < N_NODES) {
                __nv_bfloat162 p = __float22bfloat162_rn(
                    make_float2(lo0 * oscale, lo1 * oscale));
                *reinterpret_cast<unsigned*>(&g_qv[(size_t)r_lo * 128 + ofs + colm]) =
                    *reinterpret_cast<unsigned*>(&p);
            }
            if (r_hi < N_NODES) {
                __nv_bfloat162 p = __float22bfloat162_rn(
                    make_float2(hi0 * oscale, hi1 * oscale));
                *reinterpret_cast<unsigned*>(&g_qv[(size_t)r_hi * 128 + ofs + colm]) =
                    *reinterpret_cast<unsigned*>(&p);
            }
        } else {
            float* base = (half == 0) ? g_k : g_s;
            if (r_lo < N_NODES)
                *reinterpret_cast<float2*>(&base[(size_t)r_lo * 64 + colm]) =
                    make_float2(lo0, lo1);
            if (r_hi < N_NODES)
                *reinterpret_cast<float2*>(&base[(size_t)r_hi * 64 + colm]) =
                    make_float2(hi0, hi1);
        }
    }
}

// ---------------- CSR aggregation + epilogue + BN stats ----------------------
// gate = sigmoid(k+q) = 0.5*tanh(0.5k + 0.5q) + 0.5 ; q stored pre-halved.
// unroll-4 body (R7 form — measured fastest; unroll-8 regressed).
#define AGG_BLOCKS 1024
#define AGG_WARPS 8

__global__ void __launch_bounds__(256) agg_kernel(int layer,
                                                  const float* __restrict__ bconv_l) {
    int lane = threadIdx.x & 31;
    int w = threadIdx.x >> 5;
    int gw = blockIdx.x * AGG_WARPS + w;
    int nwarps = gridDim.x * AGG_WARPS;

    float2 bc = reinterpret_cast<const float2*>(bconv_l)[lane];

    float lsum0 = 0.f, lsum1 = 0.f, lssq0 = 0.f, lssq1 = 0.f;

    const unsigned int* qv32 = reinterpret_cast<const unsigned int*>(g_qv);

    for (int node = gw; node < N_NODES; node += nwarps) {
        float2 kk = reinterpret_cast<const float2*>(g_k + (size_t)node * 64)[lane];
        float k05x = 0.5f * kk.x, k05y = 0.5f * kk.y;
        float ax = 0.f, ay = 0.f;
        int e0 = g_off[node], e1 = g_off[node + 1];
        for (int base = e0; base < e1; base += 32) {
            int cnt = min(32, e1 - base);
            int sidx = (base + lane < e1) ? __ldg(&g_esrc[base + lane]) : 0;
            int j = 0;
            for (; j + 4 <= cnt; j += 4) {
                int s0 = __shfl_sync(0xffffffffu, sidx, j + 0);
                int s1 = __shfl_sync(0xffffffffu, sidx, j + 1);
                int s2 = __shfl_sync(0xffffffffu, sidx, j + 2);
                int s3 = __shfl_sync(0xffffffffu, sidx, j + 3);
                unsigned int qb0 = qv32[(size_t)s0 * 64 + lane];
                unsigned int vb0 = qv32[(size_t)s0 * 64 + 32 + lane];
                unsigned int qb1 = qv32[(size_t)s1 * 64 + lane];
                unsigned int vb1 = qv32[(size_t)s1 * 64 + 32 + lane];
                unsigned int qb2 = qv32[(size_t)s2 * 64 + lane];
                unsigned int vb2 = qv32[(size_t)s2 * 64 + 32 + lane];
                unsigned int qb3 = qv32[(size_t)s3 * 64 + lane];
                unsigned int vb3 = qv32[(size_t)s3 * 64 + 32 + lane];
                float2 q0 = bf2f(qb0), v0 = bf2f(vb0);
                float2 q1 = bf2f(qb1), v1 = bf2f(vb1);
                float2 q2 = bf2f(qb2), v2 = bf2f(vb2);
                float2 q3 = bf2f(qb3), v3 = bf2f(vb3);
                ax = fmaf(v0.x, fmaf(tanh_fast(k05x + q0.x), 0.5f, 0.5f), ax);
                ay = fmaf(v0.y, fmaf(tanh_fast(k05y + q0.y), 0.5f, 0.5f), ay);
                ax = fmaf(v1.x, fmaf(tanh_fast(k05x + q1.x), 0.5f, 0.5f), ax);
                ay = fmaf(v1.y, fmaf(tanh_fast(k05y + q1.y), 0.5f, 0.5f), ay);
                ax = fmaf(v2.x, fmaf(tanh_fast(k05x + q2.x), 0.5f, 0.5f), ax);
                ay = fmaf(v2.y, fmaf(tanh_fast(k05y + q2.y), 0.5f, 0.5f), ay);
                ax = fmaf(v3.x, fmaf(tanh_fast(k05x + q3.x), 0.5f, 0.5f), ax);
                ay = fmaf(v3.y, fmaf(tanh_fast(k05y + q3.y), 0.5f, 0.5f), ay);
            }
            for (; j < cnt; j++) {
                int s = __shfl_sync(0xffffffffu, sidx, j);
                float2 qq = bf2f(qv32[(size_t)s * 64 + lane]);
                float2 vv = bf2f(qv32[(size_t)s * 64 + 32 + lane]);
                ax = fmaf(vv.x, fmaf(tanh_fast(k05x + qq.x), 0.5f, 0.5f), ax);
                ay = fmaf(vv.y, fmaf(tanh_fast(k05y + qq.y), 0.5f, 0.5f), ay);
            }
        }
        float2 sv = reinterpret_cast<const float2*>(g_s + (size_t)node * 64)[lane];
        float t0 = fmaxf(ax + sv.x + bc.x, 0.f);
        float t1 = fmaxf(ay + sv.y + bc.y, 0.f);
        reinterpret_cast<float2*>(g_h + (size_t)node * 64)[lane] = make_float2(t0, t1);
        lsum0 += t0; lsum1 += t1;
        lssq0 += t0 * t0;
        lssq1 += t1 * t1;
    }

    __shared__ float rs[AGG_WARPS][D];
    __shared__ float rq[AGG_WARPS][D];
    rs[w][2 * lane] = lsum0; rs[w][2 * lane + 1] = lsum1;
    rq[w][2 * lane] = lssq0; rq[w][2 * lane + 1] = lssq1;
    __syncthreads();
    if (threadIdx.x < D) {
        double a = 0.0, b = 0.0;
#pragma unroll
        for (int ww = 0; ww < AGG_WARPS; ww++) {
            a += (double)rs[ww][threadIdx.x];
            b += (double)rq[ww][threadIdx.x];
        }
        atomicAdd(&g_sum[layer][threadIdx.x], a);
        atomicAdd(&g_sumsq[layer][threadIdx.x], b);
    }
}

// ---------------- BN params for pooling (layer N_LAYERS-1) -------------------
__global__ void bnparam_kernel(const float* __restrict__ gamma_l,
                               const float* __restrict__ beta_l) {
    int f = threadIdx.x;
    double mean = g_sum[N_LAYERS - 1][f] / (double)N_NODES;
    double var  = g_sumsq[N_LAYERS - 1][f] / (double)N_NODES - mean * mean;
    float a = (float)(1.0 / sqrt(var + (double)BN_EPS)) * gamma_l[f];
    g_pa[f] = a;
    g_pb[f] = beta_l[f] - (float)mean * a;
}

// ---------------- pooling (applies final BN on load) -------------------------
__global__ void pool_kernel(const int* __restrict__ batch) {
    int i = blockIdx.x * blockDim.x + threadIdx.x;
    if (i >= NV) return;
    int n = i >> 6;
    int f = i & 63;
    int b = batch[n];
    float hn = g_h[i] * g_pa[f] + g_pb[f];
    atomicAdd(&g_pool[b * 64 + f], hn);
    if (f == 0) atomicAdd(&g_cnt[b], 1.f);
}

// ---------------- final: pooled @ Wlin + blin, softmax -----------------------
__global__ void final_kernel(const float* __restrict__ Wlin,
                             const float* __restrict__ blin,
                             float* __restrict__ out) {
    __shared__ float sW[D * N_CLASSES];
    __shared__ float sb[N_CLASSES];
    int tid = threadIdx.x;
    for (int i = tid; i < D * N_CLASSES; i += blockDim.x) sW[i] = Wlin[i];
    if (tid < N_CLASSES) sb[tid] = blin[tid];
    __syncthreads();

    int g = tid;
    float cnt = fmaxf(g_cnt[g], 1.f);
    float inv = 1.f / cnt;
    float logits[N_CLASSES];
#pragma unroll
    for (int c = 0; c < N_CLASSES; c++) logits[c] = sb[c];
    for (int f = 0; f < D; f++) {
        float p = g_pool[g * 64 + f] * inv;
#pragma unroll
        for (int c = 0; c < N_CLASSES; c++)
            logits[c] += p * sW[f * N_CLASSES + c];
    }
    float mx = logits[0];
#pragma unroll
    for (int c = 1; c < N_CLASSES; c++) mx = fmaxf(mx, logits[c]);
    float sum = 0.f;
#pragma unroll
    for (int c = 0; c < N_CLASSES; c++) {
        logits[c] = expf(logits[c] - mx);
        sum += logits[c];
    }
    float isum = 1.f / sum;
#pragma unroll
    for (int c = 0; c < N_CLASSES; c++)
        out[g * N_CLASSES + c] = logits[c] * isum;
}

// ---------------- launch -----------------------------------------------------
extern "C" void kernel_launch(void* const* d_in, const int* in_sizes, int n_in,
                              void* d_out, int out_size) {
    const float* X     = (const float*)d_in[0];
    const int*   ei    = (const int*)d_in[1];
    const int*   batch = (const int*)d_in[2];
    const float* Wk    = (const float*)d_in[3];
    const float* Wq    = (const float*)d_in[4];
    const float* Wv    = (const float*)d_in[5];
    const float* Ws    = (const float*)d_in[6];
    const float* bk    = (const float*)d_in[7];
    const float* bq    = (const float*)d_in[8];
    const float* bv    = (const float*)d_in[9];
    const float* bconv = (const float*)d_in[10];
    const float* gamma = (const float*)d_in[11];
    const float* beta  = (const float*)d_in[12];
    const float* Wlin  = (const float*)d_in[13];
    const float* blin  = (const float*)d_in[14];
    float*       out   = (float*)d_out;

    static int smem_set = 0;
    if (!smem_set) {
        cudaFuncSetAttribute(gemm4_kernel,
                             cudaFuncAttributeMaxDynamicSharedMemorySize, GEMM_SMEM);
        smem_set = 1;
    }

    dim3 gemm_grid((N_NODES + GEMM_ROWS - 1) / GEMM_ROWS, 2);
    int edge_blocks = (N_EDGES + 255) / 256;

    csr_zero_kernel<<<128, 256>>>();
    csr_hist_kernel<<<edge_blocks, 256>>>(ei);
    csr_scan_kernel<<<1, 1024>>>();
    gemm4_kernel<<<gemm_grid, 256, GEMM_SMEM>>>(
        X, 1, 0,
        Wk, Wq, Wv, Ws, bk, bq, bv, gamma, beta);
    csr_scatter_kernel<<<edge_blocks, 256>>>(ei);
    agg_kernel<<<AGG_BLOCKS, 256>>>(0, bconv);

    for (int l = 1; l < N_LAYERS; l++) {
        gemm4_kernel<<<gemm_grid, 256, GEMM_SMEM>>>(
            X, 0, l - 1,
            Wk + l * D * D, Wq + l * D * D, Wv + l * D * D, Ws + l * D * D,
            bk + l * D, bq + l * D, bv + l * D,
            gamma + (l - 1) * D, beta + (l - 1) * D);
        agg_kernel<<<AGG_BLOCKS, 256>>>(l, bconv + l * D);
    }

    bnparam_kernel<<<1, 64>>>(gamma + (N_LAYERS - 1) * D, beta + (N_LAYERS - 1) * D);
    pool_kernel<<<(NV + 255) / 256, 256>>>(batch);
    final_kernel<<<1, 256>>>(Wlin, blin, out);
}

// round 12
// speedup vs baseline: 1.4490x; 1.0811x over previous
#include <cuda_runtime.h>
#include <cuda_bf16.h>
#include <math.h>

#define N_NODES 50000
#define N_EDGES 800000
#define D       64
#define N_LAYERS 5
#define N_GRAPHS 256
#define N_CLASSES 10
#define BN_EPS   1e-5f
#define NV (N_NODES * D)

// ---------------- scratch (device globals) ----------------------------------
__device__ float  g_h[NV];
__device__ float  g_k[NV];
// interleaved q/v: per node 64 words; word 2p = q-pair(2p,2p+1) (pre-halved),
// word 2p+1 = v-pair(2p,2p+1). uint2-aligned.
__device__ uint2  g_qv[N_NODES * 32];
__device__ float  g_s[NV];
__device__ double g_sum[N_LAYERS][D];
__device__ double g_sumsq[N_LAYERS][D];
__device__ float  g_pool[N_GRAPHS * D];
__device__ float  g_pa[D], g_pb[D];
// CSR
__device__ int g_deg[N_NODES + 1];
__device__ int g_off[N_NODES + 1];
__device__ int g_pos[N_NODES];
__device__ int g_esrc[N_EDGES];

// ---------------- helpers -----------------------------------------------------
__device__ __forceinline__ float tanh_fast(float x) {
    float y;
    asm("tanh.approx.f32 %0, %1;" : "=f"(y) : "f"(x));
    return y;
}
__device__ __forceinline__ float to_tf32(float x) {
    float y;
    asm("cvt.rna.tf32.f32 %0, %1;" : "=f"(y) : "f"(x));
    return y;
}
__device__ __forceinline__ void mma_tf32(float* d,
                                         unsigned a0, unsigned a1, unsigned a2, unsigned a3,
                                         unsigned b0, unsigned b1) {
    asm volatile(
        "mma.sync.aligned.m16n8k8.row.col.f32.tf32.tf32.f32 "
        "{%0,%1,%2,%3}, {%4,%5,%6,%7}, {%8,%9}, {%0,%1,%2,%3};"
        : "+f"(d[0]), "+f"(d[1]), "+f"(d[2]), "+f"(d[3])
        : "r"(a0), "r"(a1), "r"(a2), "r"(a3), "r"(b0), "r"(b1));
}
__device__ __forceinline__ unsigned fbits(float x) { return __float_as_uint(x); }
__device__ __forceinline__ float2 bf2f(unsigned int bits) {
    __nv_bfloat162 b = *reinterpret_cast<__nv_bfloat162*>(&bits);
    return __bfloat1622float2(b);
}

// ---------------- CSR build --------------------------------------------------
__global__ void csr_zero_kernel() {
    int i = blockIdx.x * blockDim.x + threadIdx.x;
    int stride = gridDim.x * blockDim.x;
    for (int j = i; j <= N_NODES; j += stride) g_deg[j] = 0;
    for (int j = i; j < N_LAYERS * D; j += stride) {
        (&g_sum[0][0])[j] = 0.0;
        (&g_sumsq[0][0])[j] = 0.0;
    }
}

__global__ void csr_hist_kernel(const int* __restrict__ ei) {
    int e = blockIdx.x * blockDim.x + threadIdx.x;
    if (e < N_EDGES) atomicAdd(&g_deg[ei[N_EDGES + e]], 1);
}

__global__ void csr_scan_kernel() {   // single block, 1024 threads
    const int T = 1024;
    const int chunk = (N_NODES + T - 1) / T;
    int t = threadIdx.x;
    int start = t * chunk;
    int end = start + chunk; if (end > N_NODES) end = N_NODES;
    int sum = 0;
    for (int i = start; i < end; i++) sum += g_deg[i];
    __shared__ int sh[T];
    sh[t] = sum;
    __syncthreads();
    for (int ofs = 1; ofs < T; ofs <<= 1) {
        int v = (t >= ofs) ? sh[t - ofs] : 0;
        __syncthreads();
        sh[t] += v;
        __syncthreads();
    }
    int run = sh[t] - sum;   // exclusive prefix
    for (int i = start; i < end; i++) {
        int d = g_deg[i];
        g_off[i] = run;
        g_pos[i] = run;
        run += d;
    }
    if (t == T - 1) g_off[N_NODES] = run;
}

__global__ void csr_scatter_kernel(const int* __restrict__ ei) {
    int e = blockIdx.x * blockDim.x + threadIdx.x;
    if (e >= N_EDGES) return;
    int src = ei[e];
    int dst = ei[N_EDGES + e];
    int p = atomicAdd(&g_pos[dst], 1);
    g_esrc[p] = src;
}

// ---------------- fused GEMM on tensor cores (tf32 mma.sync) -----------------
// grid (ceil(N/64), 2). blockIdx.y=0 -> [Wk|Wq], =1 -> [Wv|Ws]. 256 threads.
// Bank-conflict-free pads: sW stride 136 (≡8 mod 32), sH stride 68 (≡4 mod 32).
#define GEMM_ROWS 64
#define SW_STRIDE 136
#define SW_ELEMS (64 * SW_STRIDE)
#define SH_PAD 68
#define SH_ELEMS (64 * SH_PAD)
#define GEMM_SMEM ((SW_ELEMS + SH_ELEMS) * 4)

__global__ void __launch_bounds__(256, 4) gemm4_kernel(
                             const float* __restrict__ X, int use_x, int prev,
                             const float* __restrict__ Wk,
                             const float* __restrict__ Wq,
                             const float* __restrict__ Wv,
                             const float* __restrict__ Ws,
                             const float* __restrict__ bkl,
                             const float* __restrict__ bql,
                             const float* __restrict__ bvl,
                             const float* __restrict__ gamma_prev,
                             const float* __restrict__ beta_prev) {
    extern __shared__ float smem[];
    float* sW = smem;              // [64 k][136] tf32 (cols 0..127 used)
    float* sH = smem + SW_ELEMS;   // [64 r][68]  tf32
    __shared__ float sA[D], sB[D];

    int tid = threadIdx.x;
    int r0 = blockIdx.x * GEMM_ROWS;
    int half = blockIdx.y;        // 0 -> (k,q), 1 -> (v,s)

    if (tid < D) {
        if (use_x) {
            sA[tid] = 1.f; sB[tid] = 0.f;
        } else {
            double mean = g_sum[prev][tid] / (double)N_NODES;
            double var  = g_sumsq[prev][tid] / (double)N_NODES - mean * mean;
            float a = (float)(1.0 / sqrt(var + (double)BN_EPS)) * gamma_prev[tid];
            sA[tid] = a;
            sB[tid] = beta_prev[tid] - (float)mean * a;
        }
    }
    __syncthreads();

    const float* hin = use_x ? X : g_h;
    const float* W0 = half ? Wv : Wk;
    const float* W1 = half ? Ws : Wq;
    // W panel -> smem (tf32-rounded). Row i: cols [0..63] from W0, [64..127] from W1.
    for (int idx = tid; idx < 64 * 32; idx += 256) {
        int i  = idx >> 5;
        int c4 = idx & 31;
        const float* Wsel = (c4 < 16) ? W0 : W1;
        float4 wv = reinterpret_cast<const float4*>(Wsel)[i * 16 + (c4 & 15)];
        wv.x = to_tf32(wv.x); wv.y = to_tf32(wv.y);
        wv.z = to_tf32(wv.z); wv.w = to_tf32(wv.w);
        reinterpret_cast<float4*>(&sW[i * SW_STRIDE])[c4] = wv;
    }
    // H tile -> smem (BN applied, tf32-rounded)
    for (int idx = tid; idx < GEMM_ROWS * 64; idx += 256) {
        int r = idx >> 6, c = idx & 63;
        int gr = r0 + r;
        float hv = (gr < N_NODES) ? hin[gr * 64 + c] : 0.f;
        sH[r * SH_PAD + c] = to_tf32(hv * sA[c] + sB[c]);
    }
    __syncthreads();

    int w = tid >> 5, lane = tid & 31;
    int mw = w & 3;               // m-tile 0..3
    int nh = w >> 2;              // n-half 0..1
    int m0 = mw * 16;
    int g = lane >> 2, t = lane & 3;

    float acc[8][4];
#pragma unroll
    for (int nt = 0; nt < 8; nt++)
#pragma unroll
        for (int c = 0; c < 4; c++) acc[nt][c] = 0.f;

#pragma unroll
    for (int kk = 0; kk < 8; kk++) {
        int k0 = kk * 8;
        unsigned a0 = fbits(sH[(m0 + g) * SH_PAD + k0 + t]);
        unsigned a1 = fbits(sH[(m0 + g + 8) * SH_PAD + k0 + t]);
        unsigned a2 = fbits(sH[(m0 + g) * SH_PAD + k0 + t + 4]);
        unsigned a3 = fbits(sH[(m0 + g + 8) * SH_PAD + k0 + t + 4]);
#pragma unroll
        for (int nt = 0; nt < 8; nt++) {
            int n0 = nh * 64 + nt * 8;
            unsigned b0 = fbits(sW[(k0 + t) * SW_STRIDE + n0 + g]);
            unsigned b1 = fbits(sW[(k0 + t + 4) * SW_STRIDE + n0 + g]);
            mma_tf32(acc[nt], a0, a1, a2, a3, b0, b1);
        }
    }

    //  half0,nh0 -> k (fp32,bk)   half0,nh1 -> q (bf16 *0.5, bq, qv word colm+0)
    //  half1,nh0 -> v (bf16,bv, qv word colm+1)   half1,nh1 -> s (fp32, 0)
    int is_bf16 = (half == 0) ? nh : (1 - nh);
    const float* bp = (half == 0) ? ((nh == 0) ? bkl : bql)
                                  : ((nh == 0) ? bvl : nullptr);
    float oscale = (half == 0 && nh == 1) ? 0.5f : 1.f;
    int word_ofs = (half == 0) ? 0 : 1;   // q pair word / v pair word

    int r_lo = r0 + m0 + g;
    int r_hi = r_lo + 8;

    unsigned* qvw = reinterpret_cast<unsigned*>(g_qv);

#pragma unroll
    for (int nt = 0; nt < 8; nt++) {
        int colm = nt * 8 + 2 * t;        // col within matrix (0..62, even)
        float b0v = bp ? bp[colm] : 0.f;
        float b1v = bp ? bp[colm + 1] : 0.f;
        float lo0 = acc[nt][0] + b0v, lo1 = acc[nt][1] + b1v;
        float hi0 = acc[nt][2] + b0v, hi1 = acc[nt][3] + b1v;
        if (is_bf16) {
            if (r_lo < N_NODES) {
                __nv_bfloat162 p = __float22bfloat162_rn(
                    make_float2(lo0 * oscale, lo1 * oscale));
                qvw[(size_t)r_lo * 64 + colm + word_ofs] =
                    *reinterpret_cast<unsigned*>(&p);
            }
            if (r_hi < N_NODES) {
                __nv_bfloat162 p = __float22bfloat162_rn(
                    make_float2(hi0 * oscale, hi1 * oscale));
                qvw[(size_t)r_hi * 64 + colm + word_ofs] =
                    *reinterpret_cast<unsigned*>(&p);
            }
        } else {
            float* base = (half == 0) ? g_k : g_s;
            if (r_lo < N_NODES)
                *reinterpret_cast<float2*>(&base[(size_t)r_lo * 64 + colm]) =
                    make_float2(lo0, lo1);
            if (r_hi < N_NODES)
                *reinterpret_cast<float2*>(&base[(size_t)r_hi * 64 + colm]) =
                    make_float2(hi0, hi1);
        }
    }
}

// ---------------- CSR aggregation + epilogue + BN stats ----------------------
// gate = sigmoid(k+q) = 0.5*tanh(0.5k + 0.5q) + 0.5 ; q stored pre-halved.
// One LDG.64 per lane per edge (interleaved q/v pairs).
#define AGG_BLOCKS 1024
#define AGG_WARPS 8

__global__ void __launch_bounds__(256) agg_kernel(int layer,
                                                  const float* __restrict__ bconv_l) {
    int lane = threadIdx.x & 31;
    int w = threadIdx.x >> 5;
    int gw = blockIdx.x * AGG_WARPS + w;
    int nwarps = gridDim.x * AGG_WARPS;

    float2 bc = reinterpret_cast<const float2*>(bconv_l)[lane];

    float lsum0 = 0.f, lsum1 = 0.f, lssq0 = 0.f, lssq1 = 0.f;

    for (int node = gw; node < N_NODES; node += nwarps) {
        float2 kk = reinterpret_cast<const float2*>(g_k + (size_t)node * 64)[lane];
        float k05x = 0.5f * kk.x, k05y = 0.5f * kk.y;
        float ax = 0.f, ay = 0.f;
        int e0 = g_off[node], e1 = g_off[node + 1];
        for (int base = e0; base < e1; base += 32) {
            int cnt = min(32, e1 - base);
            int sidx = (base + lane < e1) ? __ldg(&g_esrc[base + lane]) : 0;
            int j = 0;
            for (; j + 4 <= cnt; j += 4) {
                int s0 = __shfl_sync(0xffffffffu, sidx, j + 0);
                int s1 = __shfl_sync(0xffffffffu, sidx, j + 1);
                int s2 = __shfl_sync(0xffffffffu, sidx, j + 2);
                int s3 = __shfl_sync(0xffffffffu, sidx, j + 3);
                uint2 u0 = g_qv[(size_t)s0 * 32 + lane];
                uint2 u1 = g_qv[(size_t)s1 * 32 + lane];
                uint2 u2 = g_qv[(size_t)s2 * 32 + lane];
                uint2 u3 = g_qv[(size_t)s3 * 32 + lane];
                float2 q0 = bf2f(u0.x), v0 = bf2f(u0.y);
                float2 q1 = bf2f(u1.x), v1 = bf2f(u1.y);
                float2 q2 = bf2f(u2.x), v2 = bf2f(u2.y);
                float2 q3 = bf2f(u3.x), v3 = bf2f(u3.y);
                ax = fmaf(v0.x, fmaf(tanh_fast(k05x + q0.x), 0.5f, 0.5f), ax);
                ay = fmaf(v0.y, fmaf(tanh_fast(k05y + q0.y), 0.5f, 0.5f), ay);
                ax = fmaf(v1.x, fmaf(tanh_fast(k05x + q1.x), 0.5f, 0.5f), ax);
                ay = fmaf(v1.y, fmaf(tanh_fast(k05y + q1.y), 0.5f, 0.5f), ay);
                ax = fmaf(v2.x, fmaf(tanh_fast(k05x + q2.x), 0.5f, 0.5f), ax);
                ay = fmaf(v2.y, fmaf(tanh_fast(k05y + q2.y), 0.5f, 0.5f), ay);
                ax = fmaf(v3.x, fmaf(tanh_fast(k05x + q3.x), 0.5f, 0.5f), ax);
                ay = fmaf(v3.y, fmaf(tanh_fast(k05y + q3.y), 0.5f, 0.5f), ay);
            }
            for (; j < cnt; j++) {
                int s = __shfl_sync(0xffffffffu, sidx, j);
                uint2 u = g_qv[(size_t)s * 32 + lane];
                float2 qq = bf2f(u.x), vv = bf2f(u.y);
                ax = fmaf(vv.x, fmaf(tanh_fast(k05x + qq.x), 0.5f, 0.5f), ax);
                ay = fmaf(vv.y, fmaf(tanh_fast(k05y + qq.y), 0.5f, 0.5f), ay);
            }
        }
        float2 sv = reinterpret_cast<const float2*>(g_s + (size_t)node * 64)[lane];
        float t0 = fmaxf(ax + sv.x + bc.x, 0.f);
        float t1 = fmaxf(ay + sv.y + bc.y, 0.f);
        reinterpret_cast<float2*>(g_h + (size_t)node * 64)[lane] = make_float2(t0, t1);
        lsum0 += t0; lsum1 += t1;
        lssq0 += t0 * t0;
        lssq1 += t1 * t1;
    }

    __shared__ float rs[AGG_WARPS][D];
    __shared__ float rq[AGG_WARPS][D];
    rs[w][2 * lane] = lsum0; rs[w][2 * lane + 1] = lsum1;
    rq[w][2 * lane] = lssq0; rq[w][2 * lane + 1] = lssq1;
    __syncthreads();
    if (threadIdx.x < D) {
        double a = 0.0, b = 0.0;
#pragma unroll
        for (int ww = 0; ww < AGG_WARPS; ww++) {
            a += (double)rs[ww][threadIdx.x];
            b += (double)rq[ww][threadIdx.x];
        }
        atomicAdd(&g_sum[layer][threadIdx.x], a);
        atomicAdd(&g_sumsq[layer][threadIdx.x], b);
    }
}

// ---------------- BN params for pooling (layer N_LAYERS-1) -------------------
__global__ void bnparam_kernel(const float* __restrict__ gamma_l,
                               const float* __restrict__ beta_l) {
    int f = threadIdx.x;
    double mean = g_sum[N_LAYERS - 1][f] / (double)N_NODES;
    double var  = g_sumsq[N_LAYERS - 1][f] / (double)N_NODES - mean * mean;
    float a = (float)(1.0 / sqrt(var + (double)BN_EPS)) * gamma_l[f];
    g_pa[f] = a;
    g_pb[f] = beta_l[f] - (float)mean * a;
}

// ---------------- pooling: one block per graph, no atomics --------------------
// batch is sorted; binary-search the node range of this graph.
__global__ void pool_kernel(const int* __restrict__ batch) {
    __shared__ int s_start, s_end;
    int g = blockIdx.x;
    int tid = threadIdx.x;
    if (tid == 0) {
        int lo = 0, hi = N_NODES;
        while (lo < hi) { int m = (lo + hi) >> 1; if (batch[m] < g) lo = m + 1; else hi = m; }
        s_start = lo;
        lo = s_start; hi = N_NODES;
        while (lo < hi) { int m = (lo + hi) >> 1; if (batch[m] < g + 1) lo = m + 1; else hi = m; }
        s_end = lo;
    }
    __syncthreads();
    int start = s_start, end = s_end;
    int f = tid & 63;
    int rb = tid >> 6;            // 0..3
    float sum = 0.f;
    for (int n = start + rb; n < end; n += 4)
        sum += g_h[(size_t)n * 64 + f];
    __shared__ float red[4][D];
    red[rb][f] = sum;
    __syncthreads();
    if (tid < D) {
        float tot = red[0][f] + red[1][f] + red[2][f] + red[3][f];
        int cnt = end - start;
        float pooled = (cnt > 0) ? (g_pa[f] * (tot / (float)cnt) + g_pb[f]) : 0.f;
        g_pool[g * D + f] = pooled;
    }
}

// ---------------- final: pooled @ Wlin + blin, softmax -----------------------
__global__ void final_kernel(const float* __restrict__ Wlin,
                             const float* __restrict__ blin,
                             float* __restrict__ out) {
    __shared__ float sW[D * N_CLASSES];
    __shared__ float sb[N_CLASSES];
    int tid = threadIdx.x;
    for (int i = tid; i < D * N_CLASSES; i += blockDim.x) sW[i] = Wlin[i];
    if (tid < N_CLASSES) sb[tid] = blin[tid];
    __syncthreads();

    int g = tid;
    float logits[N_CLASSES];
#pragma unroll
    for (int c = 0; c < N_CLASSES; c++) logits[c] = sb[c];
    for (int f = 0; f < D; f++) {
        float p = g_pool[g * D + f];
#pragma unroll
        for (int c = 0; c < N_CLASSES; c++)
            logits[c] += p * sW[f * N_CLASSES + c];
    }
    float mx = logits[0];
#pragma unroll
    for (int c = 1; c < N_CLASSES; c++) mx = fmaxf(mx, logits[c]);
    float sum = 0.f;
#pragma unroll
    for (int c = 0; c < N_CLASSES; c++) {
        logits[c] = expf(logits[c] - mx);
        sum += logits[c];
    }
    float isum = 1.f / sum;
#pragma unroll
    for (int c = 0; c < N_CLASSES; c++)
        out[g * N_CLASSES + c] = logits[c] * isum;
}

// ---------------- launch -----------------------------------------------------
extern "C" void kernel_launch(void* const* d_in, const int* in_sizes, int n_in,
                              void* d_out, int out_size) {
    const float* X     = (const float*)d_in[0];
    const int*   ei    = (const int*)d_in[1];
    const int*   batch = (const int*)d_in[2];
    const float* Wk    = (const float*)d_in[3];
    const float* Wq    = (const float*)d_in[4];
    const float* Wv    = (const float*)d_in[5];
    const float* Ws    = (const float*)d_in[6];
    const float* bk    = (const float*)d_in[7];
    const float* bq    = (const float*)d_in[8];
    const float* bv    = (const float*)d_in[9];
    const float* bconv = (const float*)d_in[10];
    const float* gamma = (const float*)d_in[11];
    const float* beta  = (const float*)d_in[12];
    const float* Wlin  = (const float*)d_in[13];
    const float* blin  = (const float*)d_in[14];
    float*       out   = (float*)d_out;

    static int smem_set = 0;
    if (!smem_set) {
        cudaFuncSetAttribute(gemm4_kernel,
                             cudaFuncAttributeMaxDynamicSharedMemorySize, GEMM_SMEM);
        smem_set = 1;
    }

    dim3 gemm_grid((N_NODES + GEMM_ROWS - 1) / GEMM_ROWS, 2);
    int edge_blocks = (N_EDGES + 255) / 256;

    csr_zero_kernel<<<128, 256>>>();
    csr_hist_kernel<<<edge_blocks, 256>>>(ei);
    csr_scan_kernel<<<1, 1024>>>();
    gemm4_kernel<<<gemm_grid, 256, GEMM_SMEM>>>(
        X, 1, 0,
        Wk, Wq, Wv, Ws, bk, bq, bv, gamma, beta);
    csr_scatter_kernel<<<edge_blocks, 256>>>(ei);
    agg_kernel<<<AGG_BLOCKS, 256>>>(0, bconv);

    for (int l = 1; l < N_LAYERS; l++) {
        gemm4_kernel<<<gemm_grid, 256, GEMM_SMEM>>>(
            X, 0, l - 1,
            Wk + l * D * D, Wq + l * D * D, Wv + l * D * D, Ws + l * D * D,
            bk + l * D, bq + l * D, bv + l * D,
            gamma + (l - 1) * D, beta + (l - 1) * D);
        agg_kernel<<<AGG_BLOCKS, 256>>>(l, bconv + l * D);
    }

    bnparam_kernel<<<1, 64>>>(gamma + (N_LAYERS - 1) * D, beta + (N_LAYERS - 1) * D);
    pool_kernel<<<N_GRAPHS, 256>>>(batch);
    final_kernel<<<1, 256>>>(Wlin, blin, out);
}

// round 13
// speedup vs baseline: 1.5179x; 1.0475x over previous
#include <cuda_runtime.h>
#include <cuda_bf16.h>
#include <math.h>

#define N_NODES 50000
#define N_EDGES 800000
#define D       64
#define N_LAYERS 5
#define N_GRAPHS 256
#define N_CLASSES 10
#define BN_EPS   1e-5f
#define NV (N_NODES * D)

// ---------------- scratch (device globals) ----------------------------------
__device__ __align__(16) float  g_h[NV];
__device__ __align__(16) float  g_k[NV];
// interleaved q/v: per node 64 words; word 2p = q-pair(2p,2p+1) (pre-halved),
// word 2p+1 = v-pair(2p,2p+1). Stored as uint4 for 16B-aligned gathers.
__device__ uint4  g_qv[N_NODES * 16];
__device__ __align__(16) float  g_s[NV];
__device__ double g_sum[N_LAYERS][D];
__device__ double g_sumsq[N_LAYERS][D];
__device__ float  g_pool[N_GRAPHS * D];
__device__ float  g_pa[D], g_pb[D];
// CSR
__device__ int g_deg[N_NODES + 1];
__device__ int g_off[N_NODES + 1];
__device__ int g_pos[N_NODES];
__device__ int g_esrc[N_EDGES];

// ---------------- helpers -----------------------------------------------------
__device__ __forceinline__ float tanh_fast(float x) {
    float y;
    asm("tanh.approx.f32 %0, %1;" : "=f"(y) : "f"(x));
    return y;
}
__device__ __forceinline__ float to_tf32(float x) {
    float y;
    asm("cvt.rna.tf32.f32 %0, %1;" : "=f"(y) : "f"(x));
    return y;
}
__device__ __forceinline__ void mma_tf32(float* d,
                                         unsigned a0, unsigned a1, unsigned a2, unsigned a3,
                                         unsigned b0, unsigned b1) {
    asm volatile(
        "mma.sync.aligned.m16n8k8.row.col.f32.tf32.tf32.f32 "
        "{%0,%1,%2,%3}, {%4,%5,%6,%7}, {%8,%9}, {%0,%1,%2,%3};"
        : "+f"(d[0]), "+f"(d[1]), "+f"(d[2]), "+f"(d[3])
        : "r"(a0), "r"(a1), "r"(a2), "r"(a3), "r"(b0), "r"(b1));
}
__device__ __forceinline__ unsigned fbits(float x) { return __float_as_uint(x); }
__device__ __forceinline__ float2 bf2f(unsigned int bits) {
    __nv_bfloat162 b = *reinterpret_cast<__nv_bfloat162*>(&bits);
    return __bfloat1622float2(b);
}

// ---------------- CSR build --------------------------------------------------
__global__ void csr_zero_kernel() {
    int i = blockIdx.x * blockDim.x + threadIdx.x;
    int stride = gridDim.x * blockDim.x;
    for (int j = i; j <= N_NODES; j += stride) g_deg[j] = 0;
    for (int j = i; j < N_LAYERS * D; j += stride) {
        (&g_sum[0][0])[j] = 0.0;
        (&g_sumsq[0][0])[j] = 0.0;
    }
}

__global__ void csr_hist_kernel(const int* __restrict__ ei) {
    int e = blockIdx.x * blockDim.x + threadIdx.x;
    if (e < N_EDGES) atomicAdd(&g_deg[ei[N_EDGES + e]], 1);
}

__global__ void csr_scan_kernel() {   // single block, 1024 threads
    const int T = 1024;
    const int chunk = (N_NODES + T - 1) / T;
    int t = threadIdx.x;
    int start = t * chunk;
    int end = start + chunk; if (end > N_NODES) end = N_NODES;
    int sum = 0;
    for (int i = start; i < end; i++) sum += g_deg[i];
    __shared__ int sh[T];
    sh[t] = sum;
    __syncthreads();
    for (int ofs = 1; ofs < T; ofs <<= 1) {
        int v = (t >= ofs) ? sh[t - ofs] : 0;
        __syncthreads();
        sh[t] += v;
        __syncthreads();
    }
    int run = sh[t] - sum;   // exclusive prefix
    for (int i = start; i < end; i++) {
        int d = g_deg[i];
        g_off[i] = run;
        g_pos[i] = run;
        run += d;
    }
    if (t == T - 1) g_off[N_NODES] = run;
}

__global__ void csr_scatter_kernel(const int* __restrict__ ei) {
    int e = blockIdx.x * blockDim.x + threadIdx.x;
    if (e >= N_EDGES) return;
    int src = ei[e];
    int dst = ei[N_EDGES + e];
    int p = atomicAdd(&g_pos[dst], 1);
    g_esrc[p] = src;
}

// ---------------- fused GEMM on tensor cores (tf32 mma.sync) -----------------
// grid (ceil(N/64), 2). blockIdx.y=0 -> [Wk|Wq], =1 -> [Wv|Ws]. 256 threads.
// warp tile 2m x 4n: 16 fragment loads per kk for 8 MMA (was 20).
#define GEMM_ROWS 64
#define SW_STRIDE 136
#define SW_ELEMS (64 * SW_STRIDE)
#define SH_PAD 68
#define SH_ELEMS (64 * SH_PAD)
#define GEMM_SMEM ((SW_ELEMS + SH_ELEMS) * 4)

__global__ void __launch_bounds__(256, 4) gemm4_kernel(
                             const float* __restrict__ X, int use_x, int prev,
                             const float* __restrict__ Wk,
                             const float* __restrict__ Wq,
                             const float* __restrict__ Wv,
                             const float* __restrict__ Ws,
                             const float* __restrict__ bkl,
                             const float* __restrict__ bql,
                             const float* __restrict__ bvl,
                             const float* __restrict__ gamma_prev,
                             const float* __restrict__ beta_prev) {
    extern __shared__ float smem[];
    float* sW = smem;              // [64 k][136] tf32 (cols 0..127 used)
    float* sH = smem + SW_ELEMS;   // [64 r][68]  tf32
    __shared__ float sA[D], sB[D];

    int tid = threadIdx.x;
    int r0 = blockIdx.x * GEMM_ROWS;
    int half = blockIdx.y;        // 0 -> (k,q), 1 -> (v,s)

    if (tid < D) {
        if (use_x) {
            sA[tid] = 1.f; sB[tid] = 0.f;
        } else {
            double mean = g_sum[prev][tid] / (double)N_NODES;
            double var  = g_sumsq[prev][tid] / (double)N_NODES - mean * mean;
            float a = (float)(1.0 / sqrt(var + (double)BN_EPS)) * gamma_prev[tid];
            sA[tid] = a;
            sB[tid] = beta_prev[tid] - (float)mean * a;
        }
    }
    __syncthreads();

    const float* hin = use_x ? X : g_h;
    const float* W0 = half ? Wv : Wk;
    const float* W1 = half ? Ws : Wq;
    for (int idx = tid; idx < 64 * 32; idx += 256) {
        int i  = idx >> 5;
        int c4 = idx & 31;
        const float* Wsel = (c4 < 16) ? W0 : W1;
        float4 wv = reinterpret_cast<const float4*>(Wsel)[i * 16 + (c4 & 15)];
        wv.x = to_tf32(wv.x); wv.y = to_tf32(wv.y);
        wv.z = to_tf32(wv.z); wv.w = to_tf32(wv.w);
        reinterpret_cast<float4*>(&sW[i * SW_STRIDE])[c4] = wv;
    }
    for (int idx = tid; idx < GEMM_ROWS * 64; idx += 256) {
        int r = idx >> 6, c = idx & 63;
        int gr = r0 + r;
        float hv = (gr < N_NODES) ? hin[gr * 64 + c] : 0.f;
        sH[r * SH_PAD + c] = to_tf32(hv * sA[c] + sB[c]);
    }
    __syncthreads();

    int w = tid >> 5, lane = tid & 31;
    int mh = w & 1;               // m-half: rows mh*32..+31 (2 m-tiles)
    int nq = w >> 1;              // n-quad: cols nq*32..+31 (4 n-tiles)
    int m0 = mh * 32;
    int g = lane >> 2, t = lane & 3;

    float acc[2][4][4];
#pragma unroll
    for (int mt = 0; mt < 2; mt++)
#pragma unroll
        for (int nt = 0; nt < 4; nt++)
#pragma unroll
            for (int c = 0; c < 4; c++) acc[mt][nt][c] = 0.f;

#pragma unroll
    for (int kk = 0; kk < 8; kk++) {
        int k0 = kk * 8;
        unsigned a[2][4];
#pragma unroll
        for (int mt = 0; mt < 2; mt++) {
            int rbase = m0 + mt * 16;
            a[mt][0] = fbits(sH[(rbase + g) * SH_PAD + k0 + t]);
            a[mt][1] = fbits(sH[(rbase + g + 8) * SH_PAD + k0 + t]);
            a[mt][2] = fbits(sH[(rbase + g) * SH_PAD + k0 + t + 4]);
            a[mt][3] = fbits(sH[(rbase + g + 8) * SH_PAD + k0 + t + 4]);
        }
#pragma unroll
        for (int nt = 0; nt < 4; nt++) {
            int n0 = nq * 32 + nt * 8;
            unsigned b0 = fbits(sW[(k0 + t) * SW_STRIDE + n0 + g]);
            unsigned b1 = fbits(sW[(k0 + t + 4) * SW_STRIDE + n0 + g]);
            mma_tf32(acc[0][nt], a[0][0], a[0][1], a[0][2], a[0][3], b0, b1);
            mma_tf32(acc[1][nt], a[1][0], a[1][1], a[1][2], a[1][3], b0, b1);
        }
    }

    //  half0,m'0 -> k (fp32,bk)   half0,m'1 -> q (bf16 *0.5, bq, qv word +0)
    //  half1,m'0 -> v (bf16,bv, qv word +1)   half1,m'1 -> s (fp32, 0)
    int mprime = nq >> 1;         // which matrix of the pair
    int is_bf16 = (half == 0) ? mprime : (1 - mprime);
    const float* bp = (half == 0) ? ((mprime == 0) ? bkl : bql)
                                  : ((mprime == 0) ? bvl : nullptr);
    float oscale = (half == 0 && mprime == 1) ? 0.5f : 1.f;
    int word_ofs = (half == 0) ? 0 : 1;

    unsigned* qvw = reinterpret_cast<unsigned*>(g_qv);

#pragma unroll
    for (int mt = 0; mt < 2; mt++) {
        int r_lo = r0 + m0 + mt * 16 + g;
        int r_hi = r_lo + 8;
#pragma unroll
        for (int nt = 0; nt < 4; nt++) {
            int c_panel = nq * 32 + nt * 8 + 2 * t;
            int colm = c_panel & 63;
            float b0v = bp ? bp[colm] : 0.f;
            float b1v = bp ? bp[colm + 1] : 0.f;
            float lo0 = acc[mt][nt][0] + b0v, lo1 = acc[mt][nt][1] + b1v;
            float hi0 = acc[mt][nt][2] + b0v, hi1 = acc[mt][nt][3] + b1v;
            if (is_bf16) {
                if (r_lo < N_NODES) {
                    __nv_bfloat162 p = __float22bfloat162_rn(
                        make_float2(lo0 * oscale, lo1 * oscale));
                    qvw[(size_t)r_lo * 64 + colm + word_ofs] =
                        *reinterpret_cast<unsigned*>(&p);
                }
                if (r_hi < N_NODES) {
                    __nv_bfloat162 p = __float22bfloat162_rn(
                        make_float2(hi0 * oscale, hi1 * oscale));
                    qvw[(size_t)r_hi * 64 + colm + word_ofs] =
                        *reinterpret_cast<unsigned*>(&p);
                }
            } else {
                float* base = (half == 0) ? g_k : g_s;
                if (r_lo < N_NODES)
                    *reinterpret_cast<float2*>(&base[(size_t)r_lo * 64 + colm]) =
                        make_float2(lo0, lo1);
                if (r_hi < N_NODES)
                    *reinterpret_cast<float2*>(&base[(size_t)r_hi * 64 + colm]) =
                        make_float2(hi0, hi1);
            }
        }
    }
}

// ---------------- CSR aggregation + epilogue + BN stats ----------------------
// Half-warp per node: 16 lanes, 4 features/lane, one LDG.128 per edge.
// gate = sigmoid(k+q) = 0.5*tanh(0.5k + 0.5q) + 0.5 ; q stored pre-halved.
#define AGG_BLOCKS 1024
#define AGG_WARPS 8
#define N_PAIRS (N_NODES / 2)

__global__ void __launch_bounds__(256, 4) agg_kernel(int layer,
                                                     const float* __restrict__ bconv_l) {
    int lane = threadIdx.x & 31;
    int w = threadIdx.x >> 5;
    int half = lane >> 4;
    int l16 = lane & 15;
    int hb = lane & 16;          // shfl source base for this half
    int gw = blockIdx.x * AGG_WARPS + w;
    int nwarps = gridDim.x * AGG_WARPS;

    float4 bc = reinterpret_cast<const float4*>(bconv_l)[l16];

    float sum0 = 0.f, sum1 = 0.f, sum2 = 0.f, sum3 = 0.f;
    float sq0 = 0.f, sq1 = 0.f, sq2 = 0.f, sq3 = 0.f;

    for (int pair = gw; pair < N_PAIRS; pair += nwarps) {
        int node = pair * 2 + half;
        float4 kk = reinterpret_cast<const float4*>(g_k + (size_t)node * 64)[l16];
        float k0 = 0.5f * kk.x, k1 = 0.5f * kk.y, k2 = 0.5f * kk.z, k3 = 0.5f * kk.w;
        float a0 = 0.f, a1 = 0.f, a2 = 0.f, a3 = 0.f;

        int e0 = g_off[node];
        int cnt = g_off[node + 1] - e0;
        int ocnt = __shfl_xor_sync(0xffffffffu, cnt, 16);
        int cmax = max(cnt, ocnt);

        for (int base = 0; base < cmax; base += 16) {
            int rem = cnt - base;    // per-half remaining (may be <= 0)
            int sidx = (l16 < rem) ? __ldg(&g_esrc[e0 + base + l16]) : 0;
            int gmax = min(16, cmax - base);   // warp-uniform
            for (int j = 0; j < gmax; j += 4) {
                int s0 = __shfl_sync(0xffffffffu, sidx, hb + j + 0);
                int s1 = __shfl_sync(0xffffffffu, sidx, hb + j + 1);
                int s2 = __shfl_sync(0xffffffffu, sidx, hb + j + 2);
                int s3 = __shfl_sync(0xffffffffu, sidx, hb + j + 3);
                uint4 u0 = make_uint4(0u, 0u, 0u, 0u);
                uint4 u1 = make_uint4(0u, 0u, 0u, 0u);
                uint4 u2 = make_uint4(0u, 0u, 0u, 0u);
                uint4 u3 = make_uint4(0u, 0u, 0u, 0u);
                if (j + 0 < rem) u0 = g_qv[(size_t)s0 * 16 + l16];
                if (j + 1 < rem) u1 = g_qv[(size_t)s1 * 16 + l16];
                if (j + 2 < rem) u2 = g_qv[(size_t)s2 * 16 + l16];
                if (j + 3 < rem) u3 = g_qv[(size_t)s3 * 16 + l16];
#pragma unroll
                for (int u = 0; u < 4; u++) {
                    uint4 uu = (u == 0) ? u0 : (u == 1) ? u1 : (u == 2) ? u2 : u3;
                    float2 q01 = bf2f(uu.x), v01 = bf2f(uu.y);
                    float2 q23 = bf2f(uu.z), v23 = bf2f(uu.w);
                    a0 = fmaf(v01.x, fmaf(tanh_fast(k0 + q01.x), 0.5f, 0.5f), a0);
                    a1 = fmaf(v01.y, fmaf(tanh_fast(k1 + q01.y), 0.5f, 0.5f), a1);
                    a2 = fmaf(v23.x, fmaf(tanh_fast(k2 + q23.x), 0.5f, 0.5f), a2);
                    a3 = fmaf(v23.y, fmaf(tanh_fast(k3 + q23.y), 0.5f, 0.5f), a3);
                }
            }
        }

        float4 sv = reinterpret_cast<const float4*>(g_s + (size_t)node * 64)[l16];
        float t0 = fmaxf(a0 + sv.x + bc.x, 0.f);
        float t1 = fmaxf(a1 + sv.y + bc.y, 0.f);
        float t2 = fmaxf(a2 + sv.z + bc.z, 0.f);
        float t3 = fmaxf(a3 + sv.w + bc.w, 0.f);
        reinterpret_cast<float4*>(g_h + (size_t)node * 64)[l16] =
            make_float4(t0, t1, t2, t3);
        sum0 += t0; sum1 += t1; sum2 += t2; sum3 += t3;
        sq0 += t0 * t0; sq1 += t1 * t1; sq2 += t2 * t2; sq3 += t3 * t3;
    }

    __shared__ float rs[AGG_WARPS][D];
    __shared__ float rq[AGG_WARPS][D];
    if (half == 0) {
        rs[w][4 * l16 + 0] = sum0; rs[w][4 * l16 + 1] = sum1;
        rs[w][4 * l16 + 2] = sum2; rs[w][4 * l16 + 3] = sum3;
        rq[w][4 * l16 + 0] = sq0;  rq[w][4 * l16 + 1] = sq1;
        rq[w][4 * l16 + 2] = sq2;  rq[w][4 * l16 + 3] = sq3;
    }
    __syncwarp();
    if (half == 1) {
        rs[w][4 * l16 + 0] += sum0; rs[w][4 * l16 + 1] += sum1;
        rs[w][4 * l16 + 2] += sum2; rs[w][4 * l16 + 3] += sum3;
        rq[w][4 * l16 + 0] += sq0;  rq[w][4 * l16 + 1] += sq1;
        rq[w][4 * l16 + 2] += sq2;  rq[w][4 * l16 + 3] += sq3;
    }
    __syncthreads();
    if (threadIdx.x < D) {
        double a = 0.0, b = 0.0;
#pragma unroll
        for (int ww = 0; ww < AGG_WARPS; ww++) {
            a += (double)rs[ww][threadIdx.x];
            b += (double)rq[ww][threadIdx.x];
        }
        atomicAdd(&g_sum[layer][threadIdx.x], a);
        atomicAdd(&g_sumsq[layer][threadIdx.x], b);
    }
}

// ---------------- BN params for pooling (layer N_LAYERS-1) -------------------
__global__ void bnparam_kernel(const float* __restrict__ gamma_l,
                               const float* __restrict__ beta_l) {
    int f = threadIdx.x;
    double mean = g_sum[N_LAYERS - 1][f] / (double)N_NODES;
    double var  = g_sumsq[N_LAYERS - 1][f] / (double)N_NODES - mean * mean;
    float a = (float)(1.0 / sqrt(var + (double)BN_EPS)) * gamma_l[f];
    g_pa[f] = a;
    g_pb[f] = beta_l[f] - (float)mean * a;
}

// ---------------- pooling: one block per graph, no atomics --------------------
__global__ void pool_kernel(const int* __restrict__ batch) {
    __shared__ int s_start, s_end;
    int g = blockIdx.x;
    int tid = threadIdx.x;
    if (tid == 0) {
        int lo = 0, hi = N_NODES;
        while (lo < hi) { int m = (lo + hi) >> 1; if (batch[m] < g) lo = m + 1; else hi = m; }
        s_start = lo;
        lo = s_start; hi = N_NODES;
        while (lo < hi) { int m = (lo + hi) >> 1; if (batch[m] < g + 1) lo = m + 1; else hi = m; }
        s_end = lo;
    }
    __syncthreads();
    int start = s_start, end = s_end;
    int f = tid & 63;
    int rb = tid >> 6;            // 0..3
    float sum = 0.f;
    for (int n = start + rb; n < end; n += 4)
        sum += g_h[(size_t)n * 64 + f];
    __shared__ float red[4][D];
    red[rb][f] = sum;
    __syncthreads();
    if (tid < D) {
        float tot = red[0][f] + red[1][f] + red[2][f] + red[3][f];
        int cnt = end - start;
        float pooled = (cnt > 0) ? (g_pa[f] * (tot / (float)cnt) + g_pb[f]) : 0.f;
        g_pool[g * D + f] = pooled;
    }
}

// ---------------- final: pooled @ Wlin + blin, softmax -----------------------
__global__ void final_kernel(const float* __restrict__ Wlin,
                             const float* __restrict__ blin,
                             float* __restrict__ out) {
    __shared__ float sW[D * N_CLASSES];
    __shared__ float sb[N_CLASSES];
    int tid = threadIdx.x;
    for (int i = tid; i < D * N_CLASSES; i += blockDim.x) sW[i] = Wlin[i];
    if (tid < N_CLASSES) sb[tid] = blin[tid];
    __syncthreads();

    int g = tid;
    float logits[N_CLASSES];
#pragma unroll
    for (int c = 0; c < N_CLASSES; c++) logits[c] = sb[c];
    for (int f = 0; f < D; f++) {
        float p = g_pool[g * D + f];
#pragma unroll
        for (int c = 0; c < N_CLASSES; c++)
            logits[c] += p * sW[f * N_CLASSES + c];
    }
    float mx = logits[0];
#pragma unroll
    for (int c = 1; c < N_CLASSES; c++) mx = fmaxf(mx, logits[c]);
    float sum = 0.f;
#pragma unroll
    for (int c = 0; c < N_CLASSES; c++) {
        logits[c] = expf(logits[c] - mx);
        sum += logits[c];
    }
    float isum = 1.f / sum;
#pragma unroll
    for (int c = 0; c < N_CLASSES; c++)
        out[g * N_CLASSES + c] = logits[c] * isum;
}

// ---------------- launch -----------------------------------------------------
extern "C" void kernel_launch(void* const* d_in, const int* in_sizes, int n_in,
                              void* d_out, int out_size) {
    const float* X     = (const float*)d_in[0];
    const int*   ei    = (const int*)d_in[1];
    const int*   batch = (const int*)d_in[2];
    const float* Wk    = (const float*)d_in[3];
    const float* Wq    = (const float*)d_in[4];
    const float* Wv    = (const float*)d_in[5];
    const float* Ws    = (const float*)d_in[6];
    const float* bk    = (const float*)d_in[7];
    const float* bq    = (const float*)d_in[8];
    const float* bv    = (const float*)d_in[9];
    const float* bconv = (const float*)d_in[10];
    const float* gamma = (const float*)d_in[11];
    const float* beta  = (const float*)d_in[12];
    const float* Wlin  = (const float*)d_in[13];
    const float* blin  = (const float*)d_in[14];
    float*       out   = (float*)d_out;

    static int smem_set = 0;
    if (!smem_set) {
        cudaFuncSetAttribute(gemm4_kernel,
                             cudaFuncAttributeMaxDynamicSharedMemorySize, GEMM_SMEM);
        smem_set = 1;
    }

    dim3 gemm_grid((N_NODES + GEMM_ROWS - 1) / GEMM_ROWS, 2);
    int edge_blocks = (N_EDGES + 255) / 256;

    csr_zero_kernel<<<128, 256>>>();
    csr_hist_kernel<<<edge_blocks, 256>>>(ei);
    csr_scan_kernel<<<1, 1024>>>();
    gemm4_kernel<<<gemm_grid, 256, GEMM_SMEM>>>(
        X, 1, 0,
        Wk, Wq, Wv, Ws, bk, bq, bv, gamma, beta);
    csr_scatter_kernel<<<edge_blocks, 256>>>(ei);
    agg_kernel<<<AGG_BLOCKS, 256>>>(0, bconv);

    for (int l = 1; l < N_LAYERS; l++) {
        gemm4_kernel<<<gemm_grid, 256, GEMM_SMEM>>>(
            X, 0, l - 1,
            Wk + l * D * D, Wq + l * D * D, Wv + l * D * D, Ws + l * D * D,
            bk + l * D, bq + l * D, bv + l * D,
            gamma + (l - 1) * D, beta + (l - 1) * D);
        agg_kernel<<<AGG_BLOCKS, 256>>>(l, bconv + l * D);
    }

    bnparam_kernel<<<1, 64>>>(gamma + (N_LAYERS - 1) * D, beta + (N_LAYERS - 1) * D);
    pool_kernel<<<N_GRAPHS, 256>>>(batch);
    final_kernel<<<1, 256>>>(Wlin, blin, out);
}

// round 14
// speedup vs baseline: 1.7014x; 1.1209x over previous
#include <cuda_runtime.h>
#include <cuda_bf16.h>
#include <math.h>

#define N_NODES 50000
#define N_EDGES 800000
#define D       64
#define N_LAYERS 5
#define N_GRAPHS 256
#define N_CLASSES 10
#define BN_EPS   1e-5f
#define NV (N_NODES * D)

// ---------------- scratch (device globals) ----------------------------------
__device__ __align__(16) float  g_h[NV];
__device__ __align__(16) float  g_k[NV];
// interleaved q/v: per node 64 words; word 2p = q-pair(2p,2p+1) (pre-halved),
// word 2p+1 = v-pair(2p,2p+1). Stored as uint4 for 16B-aligned gathers.
__device__ uint4  g_qv[N_NODES * 16];
__device__ __align__(16) float  g_s[NV];
__device__ double g_sum[N_LAYERS][D];
__device__ double g_sumsq[N_LAYERS][D];
__device__ float  g_pool[N_GRAPHS * D];
__device__ float  g_pa[D], g_pb[D];
// CSR
__device__ int g_deg[N_NODES + 1];
__device__ int g_off[N_NODES + 1];
__device__ int g_pos[N_NODES];
__device__ int g_esrc[N_EDGES];

// ---------------- helpers -----------------------------------------------------
__device__ __forceinline__ float tanh_fast(float x) {
    float y;
    asm("tanh.approx.f32 %0, %1;" : "=f"(y) : "f"(x));
    return y;
}
__device__ __forceinline__ float to_tf32(float x) {
    float y;
    asm("cvt.rna.tf32.f32 %0, %1;" : "=f"(y) : "f"(x));
    return y;
}
__device__ __forceinline__ void mma_tf32(float* d,
                                         unsigned a0, unsigned a1, unsigned a2, unsigned a3,
                                         unsigned b0, unsigned b1) {
    asm volatile(
        "mma.sync.aligned.m16n8k8.row.col.f32.tf32.tf32.f32 "
        "{%0,%1,%2,%3}, {%4,%5,%6,%7}, {%8,%9}, {%0,%1,%2,%3};"
        : "+f"(d[0]), "+f"(d[1]), "+f"(d[2]), "+f"(d[3])
        : "r"(a0), "r"(a1), "r"(a2), "r"(a3), "r"(b0), "r"(b1));
}
__device__ __forceinline__ unsigned fbits(float x) { return __float_as_uint(x); }
__device__ __forceinline__ float2 bf2f(unsigned int bits) {
    __nv_bfloat162 b = *reinterpret_cast<__nv_bfloat162*>(&bits);
    return __bfloat1622float2(b);
}

// ---------------- CSR build --------------------------------------------------
__global__ void csr_zero_kernel() {
    int i = blockIdx.x * blockDim.x + threadIdx.x;
    int stride = gridDim.x * blockDim.x;
    for (int j = i; j <= N_NODES; j += stride) g_deg[j] = 0;
    for (int j = i; j < N_LAYERS * D; j += stride) {
        (&g_sum[0][0])[j] = 0.0;
        (&g_sumsq[0][0])[j] = 0.0;
    }
}

__global__ void csr_hist_kernel(const int* __restrict__ ei) {
    int e = blockIdx.x * blockDim.x + threadIdx.x;
    if (e < N_EDGES) atomicAdd(&g_deg[ei[N_EDGES + e]], 1);
}

__global__ void csr_scan_kernel() {   // single block, 1024 threads
    const int T = 1024;
    const int chunk = (N_NODES + T - 1) / T;
    int t = threadIdx.x;
    int start = t * chunk;
    int end = start + chunk; if (end > N_NODES) end = N_NODES;
    int sum = 0;
    for (int i = start; i < end; i++) sum += g_deg[i];
    __shared__ int sh[T];
    sh[t] = sum;
    __syncthreads();
    for (int ofs = 1; ofs < T; ofs <<= 1) {
        int v = (t >= ofs) ? sh[t - ofs] : 0;
        __syncthreads();
        sh[t] += v;
        __syncthreads();
    }
    int run = sh[t] - sum;   // exclusive prefix
    for (int i = start; i < end; i++) {
        int d = g_deg[i];
        g_off[i] = run;
        g_pos[i] = run;
        run += d;
    }
    if (t == T - 1) g_off[N_NODES] = run;
}

__global__ void csr_scatter_kernel(const int* __restrict__ ei) {
    int e = blockIdx.x * blockDim.x + threadIdx.x;
    if (e >= N_EDGES) return;
    int src = ei[e];
    int dst = ei[N_EDGES + e];
    int p = atomicAdd(&g_pos[dst], 1);
    g_esrc[p] = src;
}

// ---------------- fused GEMM on tensor cores (tf32 mma.sync) -----------------
// Persistent over row tiles: grid (296, 2) = one full wave at 4 CTA/SM.
// Each block loads W + BN affine ONCE, then strides over 64-row tiles.
#define GEMM_ROWS 64
#define GEMM_GRID_X 296
#define N_ROW_TILES ((N_NODES + GEMM_ROWS - 1) / GEMM_ROWS)
#define SW_STRIDE 136
#define SW_ELEMS (64 * SW_STRIDE)
#define SH_PAD 68
#define SH_ELEMS (64 * SH_PAD)
#define GEMM_SMEM ((SW_ELEMS + SH_ELEMS) * 4)

__global__ void __launch_bounds__(256, 4) gemm4_kernel(
                             const float* __restrict__ X, int use_x, int prev,
                             const float* __restrict__ Wk,
                             const float* __restrict__ Wq,
                             const float* __restrict__ Wv,
                             const float* __restrict__ Ws,
                             const float* __restrict__ bkl,
                             const float* __restrict__ bql,
                             const float* __restrict__ bvl,
                             const float* __restrict__ gamma_prev,
                             const float* __restrict__ beta_prev) {
    extern __shared__ float smem[];
    float* sW = smem;              // [64 k][136] tf32 (cols 0..127 used)
    float* sH = smem + SW_ELEMS;   // [64 r][68]  tf32
    __shared__ float sA[D], sB[D];

    int tid = threadIdx.x;
    int half = blockIdx.y;        // 0 -> (k,q), 1 -> (v,s)

    if (tid < D) {
        if (use_x) {
            sA[tid] = 1.f; sB[tid] = 0.f;
        } else {
            double mean = g_sum[prev][tid] / (double)N_NODES;
            double var  = g_sumsq[prev][tid] / (double)N_NODES - mean * mean;
            float a = (float)(1.0 / sqrt(var + (double)BN_EPS)) * gamma_prev[tid];
            sA[tid] = a;
            sB[tid] = beta_prev[tid] - (float)mean * a;
        }
    }

    const float* hin = use_x ? X : g_h;
    const float* W0 = half ? Wv : Wk;
    const float* W1 = half ? Ws : Wq;
    for (int idx = tid; idx < 64 * 32; idx += 256) {
        int i  = idx >> 5;
        int c4 = idx & 31;
        const float* Wsel = (c4 < 16) ? W0 : W1;
        float4 wv = reinterpret_cast<const float4*>(Wsel)[i * 16 + (c4 & 15)];
        wv.x = to_tf32(wv.x); wv.y = to_tf32(wv.y);
        wv.z = to_tf32(wv.z); wv.w = to_tf32(wv.w);
        reinterpret_cast<float4*>(&sW[i * SW_STRIDE])[c4] = wv;
    }

    int w = tid >> 5, lane = tid & 31;
    int mh = w & 1;               // m-half: rows mh*32..+31 (2 m-tiles)
    int nq = w >> 1;              // n-quad: cols nq*32..+31 (4 n-tiles)
    int m0 = mh * 32;
    int g = lane >> 2, t = lane & 3;

    int mprime = nq >> 1;         // which matrix of the pair
    int is_bf16 = (half == 0) ? mprime : (1 - mprime);
    const float* bp = (half == 0) ? ((mprime == 0) ? bkl : bql)
                                  : ((mprime == 0) ? bvl : nullptr);
    float oscale = (half == 0 && mprime == 1) ? 0.5f : 1.f;
    int word_ofs = (half == 0) ? 0 : 1;
    unsigned* qvw = reinterpret_cast<unsigned*>(g_qv);

    for (int tile = blockIdx.x; tile < N_ROW_TILES; tile += GEMM_GRID_X) {
        int r0 = tile * GEMM_ROWS;
        __syncthreads();   // prior mainloop readers done before overwriting sH
        for (int idx = tid; idx < GEMM_ROWS * 64; idx += 256) {
            int r = idx >> 6, c = idx & 63;
            int gr = r0 + r;
            float hv = (gr < N_NODES) ? hin[gr * 64 + c] : 0.f;
            sH[r * SH_PAD + c] = to_tf32(hv * sA[c] + sB[c]);
        }
        __syncthreads();

        float acc[2][4][4];
#pragma unroll
        for (int mt = 0; mt < 2; mt++)
#pragma unroll
            for (int nt = 0; nt < 4; nt++)
#pragma unroll
                for (int c = 0; c < 4; c++) acc[mt][nt][c] = 0.f;

#pragma unroll
        for (int kk = 0; kk < 8; kk++) {
            int k0 = kk * 8;
            unsigned a[2][4];
#pragma unroll
            for (int mt = 0; mt < 2; mt++) {
                int rbase = m0 + mt * 16;
                a[mt][0] = fbits(sH[(rbase + g) * SH_PAD + k0 + t]);
                a[mt][1] = fbits(sH[(rbase + g + 8) * SH_PAD + k0 + t]);
                a[mt][2] = fbits(sH[(rbase + g) * SH_PAD + k0 + t + 4]);
                a[mt][3] = fbits(sH[(rbase + g + 8) * SH_PAD + k0 + t + 4]);
            }
#pragma unroll
            for (int nt = 0; nt < 4; nt++) {
                int n0 = nq * 32 + nt * 8;
                unsigned b0 = fbits(sW[(k0 + t) * SW_STRIDE + n0 + g]);
                unsigned b1 = fbits(sW[(k0 + t + 4) * SW_STRIDE + n0 + g]);
                mma_tf32(acc[0][nt], a[0][0], a[0][1], a[0][2], a[0][3], b0, b1);
                mma_tf32(acc[1][nt], a[1][0], a[1][1], a[1][2], a[1][3], b0, b1);
            }
        }

#pragma unroll
        for (int mt = 0; mt < 2; mt++) {
            int r_lo = r0 + m0 + mt * 16 + g;
            int r_hi = r_lo + 8;
#pragma unroll
            for (int nt = 0; nt < 4; nt++) {
                int c_panel = nq * 32 + nt * 8 + 2 * t;
                int colm = c_panel & 63;
                float b0v = bp ? bp[colm] : 0.f;
                float b1v = bp ? bp[colm + 1] : 0.f;
                float lo0 = acc[mt][nt][0] + b0v, lo1 = acc[mt][nt][1] + b1v;
                float hi0 = acc[mt][nt][2] + b0v, hi1 = acc[mt][nt][3] + b1v;
                if (is_bf16) {
                    if (r_lo < N_NODES) {
                        __nv_bfloat162 p = __float22bfloat162_rn(
                            make_float2(lo0 * oscale, lo1 * oscale));
                        qvw[(size_t)r_lo * 64 + colm + word_ofs] =
                            *reinterpret_cast<unsigned*>(&p);
                    }
                    if (r_hi < N_NODES) {
                        __nv_bfloat162 p = __float22bfloat162_rn(
                            make_float2(hi0 * oscale, hi1 * oscale));
                        qvw[(size_t)r_hi * 64 + colm + word_ofs] =
                            *reinterpret_cast<unsigned*>(&p);
                    }
                } else {
                    float* base = (half == 0) ? g_k : g_s;
                    if (r_lo < N_NODES)
                        *reinterpret_cast<float2*>(&base[(size_t)r_lo * 64 + colm]) =
                            make_float2(lo0, lo1);
                    if (r_hi < N_NODES)
                        *reinterpret_cast<float2*>(&base[(size_t)r_hi * 64 + colm]) =
                            make_float2(hi0, hi1);
                }
            }
        }
    }
}

// ---------------- CSR aggregation + epilogue + BN stats ----------------------
// Half-warp per node: 16 lanes, 4 features/lane, one LDG.128 per edge.
// gate = sigmoid(k+q) = 0.5*tanh(0.5k + 0.5q) + 0.5 ; q stored pre-halved.
#define AGG_BLOCKS 1024
#define AGG_WARPS 8
#define N_PAIRS (N_NODES / 2)

__global__ void __launch_bounds__(256, 4) agg_kernel(int layer,
                                                     const float* __restrict__ bconv_l) {
    int lane = threadIdx.x & 31;
    int w = threadIdx.x >> 5;
    int half = lane >> 4;
    int l16 = lane & 15;
    int hb = lane & 16;          // shfl source base for this half
    int gw = blockIdx.x * AGG_WARPS + w;
    int nwarps = gridDim.x * AGG_WARPS;

    float4 bc = reinterpret_cast<const float4*>(bconv_l)[l16];

    float sum0 = 0.f, sum1 = 0.f, sum2 = 0.f, sum3 = 0.f;
    float sq0 = 0.f, sq1 = 0.f, sq2 = 0.f, sq3 = 0.f;

    for (int pair = gw; pair < N_PAIRS; pair += nwarps) {
        int node = pair * 2 + half;
        float4 kk = reinterpret_cast<const float4*>(g_k + (size_t)node * 64)[l16];
        float k0 = 0.5f * kk.x, k1 = 0.5f * kk.y, k2 = 0.5f * kk.z, k3 = 0.5f * kk.w;
        float a0 = 0.f, a1 = 0.f, a2 = 0.f, a3 = 0.f;

        int e0 = g_off[node];
        int cnt = g_off[node + 1] - e0;
        int ocnt = __shfl_xor_sync(0xffffffffu, cnt, 16);
        int cmax = max(cnt, ocnt);

        for (int base = 0; base < cmax; base += 16) {
            int rem = cnt - base;    // per-half remaining (may be <= 0)
            int sidx = (l16 < rem) ? __ldg(&g_esrc[e0 + base + l16]) : 0;
            int gmax = min(16, cmax - base);   // warp-uniform
            for (int j = 0; j < gmax; j += 4) {
                int s0 = __shfl_sync(0xffffffffu, sidx, hb + j + 0);
                int s1 = __shfl_sync(0xffffffffu, sidx, hb + j + 1);
                int s2 = __shfl_sync(0xffffffffu, sidx, hb + j + 2);
                int s3 = __shfl_sync(0xffffffffu, sidx, hb + j + 3);
                uint4 u0 = make_uint4(0u, 0u, 0u, 0u);
                uint4 u1 = make_uint4(0u, 0u, 0u, 0u);
                uint4 u2 = make_uint4(0u, 0u, 0u, 0u);
                uint4 u3 = make_uint4(0u, 0u, 0u, 0u);
                if (j + 0 < rem) u0 = g_qv[(size_t)s0 * 16 + l16];
                if (j + 1 < rem) u1 = g_qv[(size_t)s1 * 16 + l16];
                if (j + 2 < rem) u2 = g_qv[(size_t)s2 * 16 + l16];
                if (j + 3 < rem) u3 = g_qv[(size_t)s3 * 16 + l16];
#pragma unroll
                for (int u = 0; u < 4; u++) {
                    uint4 uu = (u == 0) ? u0 : (u == 1) ? u1 : (u == 2) ? u2 : u3;
                    float2 q01 = bf2f(uu.x), v01 = bf2f(uu.y);
                    float2 q23 = bf2f(uu.z), v23 = bf2f(uu.w);
                    a0 = fmaf(v01.x, fmaf(tanh_fast(k0 + q01.x), 0.5f, 0.5f), a0);
                    a1 = fmaf(v01.y, fmaf(tanh_fast(k1 + q01.y), 0.5f, 0.5f), a1);
                    a2 = fmaf(v23.x, fmaf(tanh_fast(k2 + q23.x), 0.5f, 0.5f), a2);
                    a3 = fmaf(v23.y, fmaf(tanh_fast(k3 + q23.y), 0.5f, 0.5f), a3);
                }
            }
        }

        float4 sv = reinterpret_cast<const float4*>(g_s + (size_t)node * 64)[l16];
        float t0 = fmaxf(a0 + sv.x + bc.x, 0.f);
        float t1 = fmaxf(a1 + sv.y + bc.y, 0.f);
        float t2 = fmaxf(a2 + sv.z + bc.z, 0.f);
        float t3 = fmaxf(a3 + sv.w + bc.w, 0.f);
        reinterpret_cast<float4*>(g_h + (size_t)node * 64)[l16] =
            make_float4(t0, t1, t2, t3);
        sum0 += t0; sum1 += t1; sum2 += t2; sum3 += t3;
        sq0 += t0 * t0; sq1 += t1 * t1; sq2 += t2 * t2; sq3 += t3 * t3;
    }

    __shared__ float rs[AGG_WARPS][D];
    __shared__ float rq[AGG_WARPS][D];
    if (half == 0) {
        rs[w][4 * l16 + 0] = sum0; rs[w][4 * l16 + 1] = sum1;
        rs[w][4 * l16 + 2] = sum2; rs[w][4 * l16 + 3] = sum3;
        rq[w][4 * l16 + 0] = sq0;  rq[w][4 * l16 + 1] = sq1;
        rq[w][4 * l16 + 2] = sq2;  rq[w][4 * l16 + 3] = sq3;
    }
    __syncwarp();
    if (half == 1) {
        rs[w][4 * l16 + 0] += sum0; rs[w][4 * l16 + 1] += sum1;
        rs[w][4 * l16 + 2] += sum2; rs[w][4 * l16 + 3] += sum3;
        rq[w][4 * l16 + 0] += sq0;  rq[w][4 * l16 + 1] += sq1;
        rq[w][4 * l16 + 2] += sq2;  rq[w][4 * l16 + 3] += sq3;
    }
    __syncthreads();
    if (threadIdx.x < D) {
        double a = 0.0, b = 0.0;
#pragma unroll
        for (int ww = 0; ww < AGG_WARPS; ww++) {
            a += (double)rs[ww][threadIdx.x];
            b += (double)rq[ww][threadIdx.x];
        }
        atomicAdd(&g_sum[layer][threadIdx.x], a);
        atomicAdd(&g_sumsq[layer][threadIdx.x], b);
    }
}

// ---------------- BN params for pooling (layer N_LAYERS-1) -------------------
__global__ void bnparam_kernel(const float* __restrict__ gamma_l,
                               const float* __restrict__ beta_l) {
    int f = threadIdx.x;
    double mean = g_sum[N_LAYERS - 1][f] / (double)N_NODES;
    double var  = g_sumsq[N_LAYERS - 1][f] / (double)N_NODES - mean * mean;
    float a = (float)(1.0 / sqrt(var + (double)BN_EPS)) * gamma_l[f];
    g_pa[f] = a;
    g_pb[f] = beta_l[f] - (float)mean * a;
}

// ---------------- pooling: one block per graph, no atomics --------------------
__global__ void pool_kernel(const int* __restrict__ batch) {
    __shared__ int s_start, s_end;
    int g = blockIdx.x;
    int tid = threadIdx.x;
    if (tid == 0) {
        int lo = 0, hi = N_NODES;
        while (lo < hi) { int m = (lo + hi) >> 1; if (batch[m] < g) lo = m + 1; else hi = m; }
        s_start = lo;
        lo = s_start; hi = N_NODES;
        while (lo < hi) { int m = (lo + hi) >> 1; if (batch[m] < g + 1) lo = m + 1; else hi = m; }
        s_end = lo;
    }
    __syncthreads();
    int start = s_start, end = s_end;
    int f = tid & 63;
    int rb = tid >> 6;            // 0..3
    float sum = 0.f;
    for (int n = start + rb; n < end; n += 4)
        sum += g_h[(size_t)n * 64 + f];
    __shared__ float red[4][D];
    red[rb][f] = sum;
    __syncthreads();
    if (tid < D) {
        float tot = red[0][f] + red[1][f] + red[2][f] + red[3][f];
        int cnt = end - start;
        float pooled = (cnt > 0) ? (g_pa[f] * (tot / (float)cnt) + g_pb[f]) : 0.f;
        g_pool[g * D + f] = pooled;
    }
}

// ---------------- final: pooled @ Wlin + blin, softmax -----------------------
__global__ void final_kernel(const float* __restrict__ Wlin,
                             const float* __restrict__ blin,
                             float* __restrict__ out) {
    __shared__ float sW[D * N_CLASSES];
    __shared__ float sb[N_CLASSES];
    int tid = threadIdx.x;
    for (int i = tid; i < D * N_CLASSES; i += blockDim.x) sW[i] = Wlin[i];
    if (tid < N_CLASSES) sb[tid] = blin[tid];
    __syncthreads();

    int g = tid;
    float logits[N_CLASSES];
#pragma unroll
    for (int c = 0; c < N_CLASSES; c++) logits[c] = sb[c];
    for (int f = 0; f < D; f++) {
        float p = g_pool[g * D + f];
#pragma unroll
        for (int c = 0; c < N_CLASSES; c++)
            logits[c] += p * sW[f * N_CLASSES + c];
    }
    float mx = logits[0];
#pragma unroll
    for (int c = 1; c < N_CLASSES; c++) mx = fmaxf(mx, logits[c]);
    float sum = 0.f;
#pragma unroll
    for (int c = 0; c < N_CLASSES; c++) {
        logits[c] = expf(logits[c] - mx);
        sum += logits[c];
    }
    float isum = 1.f / sum;
#pragma unroll
    for (int c = 0; c < N_CLASSES; c++)
        out[g * N_CLASSES + c] = logits[c] * isum;
}

// ---------------- launch -----------------------------------------------------
extern "C" void kernel_launch(void* const* d_in, const int* in_sizes, int n_in,
                              void* d_out, int out_size) {
    const float* X     = (const float*)d_in[0];
    const int*   ei    = (const int*)d_in[1];
    const int*   batch = (const int*)d_in[2];
    const float* Wk    = (const float*)d_in[3];
    const float* Wq    = (const float*)d_in[4];
    const float* Wv    = (const float*)d_in[5];
    const float* Ws    = (const float*)d_in[6];
    const float* bk    = (const float*)d_in[7];
    const float* bq    = (const float*)d_in[8];
    const float* bv    = (const float*)d_in[9];
    const float* bconv = (const float*)d_in[10];
    const float* gamma = (const float*)d_in[11];
    const float* beta  = (const float*)d_in[12];
    const float* Wlin  = (const float*)d_in[13];
    const float* blin  = (const float*)d_in[14];
    float*       out   = (float*)d_out;

    static int smem_set = 0;
    if (!smem_set) {
        cudaFuncSetAttribute(gemm4_kernel,
                             cudaFuncAttributeMaxDynamicSharedMemorySize, GEMM_SMEM);
        smem_set = 1;
    }

    dim3 gemm_grid(GEMM_GRID_X, 2);
    int edge_blocks = (N_EDGES + 255) / 256;

    csr_zero_kernel<<<128, 256>>>();
    csr_hist_kernel<<<edge_blocks, 256>>>(ei);
    csr_scan_kernel<<<1, 1024>>>();
    gemm4_kernel<<<gemm_grid, 256, GEMM_SMEM>>>(
        X, 1, 0,
        Wk, Wq, Wv, Ws, bk, bq, bv, gamma, beta);
    csr_scatter_kernel<<<edge_blocks, 256>>>(ei);
    agg_kernel<<<AGG_BLOCKS, 256>>>(0, bconv);

    for (int l = 1; l < N_LAYERS; l++) {
        gemm4_kernel<<<gemm_grid, 256, GEMM_SMEM>>>(
            X, 0, l - 1,
            Wk + l * D * D, Wq + l * D * D, Wv + l * D * D, Ws + l * D * D,
            bk + l * D, bq + l * D, bv + l * D,
            gamma + (l - 1) * D, beta + (l - 1) * D);
        agg_kernel<<<AGG_BLOCKS, 256>>>(l, bconv + l * D);
    }

    bnparam_kernel<<<1, 64>>>(gamma + (N_LAYERS - 1) * D, beta + (N_LAYERS - 1) * D);
    pool_kernel<<<N_GRAPHS, 256>>>(batch);
    final_kernel<<<1, 256>>>(Wlin, blin, out);
}